// round 2
// baseline (speedup 1.0000x reference)
#include <cuda_runtime.h>
#include <math.h>

// ---------------- problem constants ----------------
constexpr int B_   = 2;
constexpr int S_   = 2048;
constexpr int H_   = 2048;
constexpr int NH_  = 16;
constexpr int NKV_ = 4;
constexpr int HD_  = 128;
constexpr int T_   = B_ * S_;      // 4096 tokens
constexpr int E_   = 8;
constexpr int I_   = 1024;
constexpr float EPS_ = 1e-5f;
constexpr float THETA_ = 500000.0f;

// ---------------- scratch (device globals; no allocations allowed) ----------------
__device__ float g_xn1   [T_ * H_];
__device__ float g_q     [T_ * NH_ * HD_];
__device__ float g_k     [T_ * NKV_ * HD_];
__device__ float g_v     [T_ * NKV_ * HD_];
__device__ float g_attn  [T_ * NH_ * HD_];
__device__ float g_hidden[T_ * H_];
__device__ float g_xn2   [T_ * H_];
__device__ float g_shact [T_ * I_];
__device__ float g_shout [T_ * H_];
__device__ float g_moeact[(size_t)E_ * T_ * I_];   // 128 MB
__device__ float g_eout  [(size_t)E_ * T_ * H_];   // 256 MB
__device__ int   g_cnt   [E_];
__device__ int   g_list  [E_ * T_];
__device__ int   g_slot_e[T_ * 2];
__device__ int   g_slot_p[T_ * 2];
__device__ float g_slot_w[T_ * 2];

// ---------------- RMSNorm ----------------
__global__ void rmsnorm_kernel(const float* __restrict__ in,
                               const float* __restrict__ w,
                               float* __restrict__ out) {
    int t = blockIdx.x;
    const float* x = in + (size_t)t * H_;
    float ss = 0.f;
    for (int i = threadIdx.x; i < H_; i += 256) { float vv = x[i]; ss += vv * vv; }
    __shared__ float red[256];
    red[threadIdx.x] = ss;
    __syncthreads();
    for (int s2 = 128; s2 > 0; s2 >>= 1) {
        if (threadIdx.x < s2) red[threadIdx.x] += red[threadIdx.x + s2];
        __syncthreads();
    }
    float rs = rsqrtf(red[0] / (float)H_ + EPS_);
    float* o = out + (size_t)t * H_;
    for (int i = threadIdx.x; i < H_; i += 256) o[i] = w[i] * x[i] * rs;
}

// ---------------- generic batched GEMM: C = A @ B (+ addend), dynamic M per batch ----------------
// A: [M,K] row-major (lda=K), B: [K,N] (ldb=N), C: [M,N]. 64x64 tile, BK=16, 256 thr, 4x4/thread.
__global__ void gemm_kernel(const float* __restrict__ A, size_t strideA,
                            const float* __restrict__ Bm, size_t strideB,
                            float* __restrict__ C, size_t strideC,
                            int M, int N, int K,
                            const float* __restrict__ addend,
                            const int* __restrict__ m_counts) {
    int z = blockIdx.z;
    if (m_counts) { int mc = m_counts[z]; if (mc < M) M = mc; }
    int m0 = blockIdx.y * 64;
    if (m0 >= M) return;
    int n0 = blockIdx.x * 64;
    A  += (size_t)z * strideA;
    Bm += (size_t)z * strideB;
    C  += (size_t)z * strideC;
    if (addend) addend += (size_t)z * strideC;

    __shared__ float As[16][68];
    __shared__ float Bs[16][64];

    int tid = threadIdx.x;
    int tx = tid & 15, ty = tid >> 4;
    int ar = tid >> 2, ac = (tid & 3) << 2;       // A tile loader: row 0..63, kcol {0,4,8,12}
    int br = tid >> 4, bc = (tid & 15) << 2;      // B tile loader

    bool avalid = (m0 + ar) < M;
    float acc[4][4] = {};

    for (int k0 = 0; k0 < K; k0 += 16) {
        float4 av = make_float4(0.f, 0.f, 0.f, 0.f);
        if (avalid) av = *(const float4*)&A[(size_t)(m0 + ar) * K + k0 + ac];
        As[ac + 0][ar] = av.x; As[ac + 1][ar] = av.y;
        As[ac + 2][ar] = av.z; As[ac + 3][ar] = av.w;
        *(float4*)&Bs[br][bc] = *(const float4*)&Bm[(size_t)(k0 + br) * N + n0 + bc];
        __syncthreads();
#pragma unroll
        for (int kk = 0; kk < 16; kk++) {
            float a_[4];
#pragma unroll
            for (int i = 0; i < 4; i++) a_[i] = As[kk][ty * 4 + i];
            float b_[4];
            *(float4*)b_ = *(float4*)&Bs[kk][tx * 4];
#pragma unroll
            for (int i = 0; i < 4; i++)
#pragma unroll
                for (int j = 0; j < 4; j++) acc[i][j] += a_[i] * b_[j];
        }
        __syncthreads();
    }
#pragma unroll
    for (int i = 0; i < 4; i++) {
        int row = m0 + ty * 4 + i;
        if (row < M) {
#pragma unroll
            for (int j = 0; j < 4; j++) {
                int col = n0 + tx * 4 + j;
                float val = acc[i][j];
                if (addend) val += addend[(size_t)row * N + col];
                C[(size_t)row * N + col] = val;
            }
        }
    }
}

// ---------------- fused gate/up GEMM + SiLU (shared expert and routed experts) ----------------
// Out[row] = silu(A[arow] @ Bg) * (A[arow] @ Bu), arow gathered via lists if given.
__global__ void gu_kernel(const float* __restrict__ A,
                          const float* __restrict__ Bg_base,
                          const float* __restrict__ Bu_base,
                          size_t strideB,
                          float* __restrict__ Out, size_t strideOut,
                          int N, int K,
                          const int* __restrict__ counts,
                          const int* __restrict__ lists) {
    int z = blockIdx.z;
    int M = counts ? counts[z] : T_;
    int m0 = blockIdx.y * 64;
    if (m0 >= M) return;
    int n0 = blockIdx.x * 64;
    const float* Bg = Bg_base + (size_t)z * strideB;
    const float* Bu = Bu_base + (size_t)z * strideB;
    Out += (size_t)z * strideOut;

    __shared__ float As[16][68];
    __shared__ float Bgs[16][64];
    __shared__ float Bus[16][64];

    int tid = threadIdx.x;
    int tx = tid & 15, ty = tid >> 4;
    int ar = tid >> 2, ac = (tid & 3) << 2;
    int br = tid >> 4, bc = (tid & 15) << 2;

    bool avalid = (m0 + ar) < M;
    int arow = 0;
    if (avalid) arow = lists ? lists[z * T_ + m0 + ar] : (m0 + ar);

    float accg[4][4] = {}, accu[4][4] = {};
    for (int k0 = 0; k0 < K; k0 += 16) {
        float4 av = make_float4(0.f, 0.f, 0.f, 0.f);
        if (avalid) av = *(const float4*)&A[(size_t)arow * K + k0 + ac];
        As[ac + 0][ar] = av.x; As[ac + 1][ar] = av.y;
        As[ac + 2][ar] = av.z; As[ac + 3][ar] = av.w;
        *(float4*)&Bgs[br][bc] = *(const float4*)&Bg[(size_t)(k0 + br) * N + n0 + bc];
        *(float4*)&Bus[br][bc] = *(const float4*)&Bu[(size_t)(k0 + br) * N + n0 + bc];
        __syncthreads();
#pragma unroll
        for (int kk = 0; kk < 16; kk++) {
            float a_[4];
#pragma unroll
            for (int i = 0; i < 4; i++) a_[i] = As[kk][ty * 4 + i];
            float bg_[4], bu_[4];
            *(float4*)bg_ = *(float4*)&Bgs[kk][tx * 4];
            *(float4*)bu_ = *(float4*)&Bus[kk][tx * 4];
#pragma unroll
            for (int i = 0; i < 4; i++)
#pragma unroll
                for (int j = 0; j < 4; j++) {
                    accg[i][j] += a_[i] * bg_[j];
                    accu[i][j] += a_[i] * bu_[j];
                }
        }
        __syncthreads();
    }
#pragma unroll
    for (int i = 0; i < 4; i++) {
        int row = m0 + ty * 4 + i;
        if (row < M) {
#pragma unroll
            for (int j = 0; j < 4; j++) {
                int col = n0 + tx * 4 + j;
                float gv = accg[i][j], uv = accu[i][j];
                float act = gv / (1.f + expf(-gv)) * uv;   // silu(g)*u
                Out[(size_t)row * N + col] = act;
            }
        }
    }
}

// ---------------- RoPE (in place on q or k) ----------------
__global__ void rope_kernel(float* __restrict__ q, int nheads) {
    int idx = blockIdx.x * blockDim.x + threadIdx.x;
    int total = T_ * nheads * (HD_ / 2);
    if (idx >= total) return;
    int d = idx & 63;
    int rest = idx >> 6;
    int h = rest % nheads;
    int t = rest / nheads;
    int pos = t % S_;                           // t = b*S + s
    float inv = powf(THETA_, -(float)d / 64.0f);
    float ang = (float)pos * inv;
    float c = cosf(ang), sn = sinf(ang);
    float* base = q + (size_t)t * nheads * HD_ + h * HD_;
    float x1 = base[d], x2 = base[d + 64];
    base[d]      = x1 * c - x2 * sn;
    base[d + 64] = x2 * c + x1 * sn;
}

// ---------------- flash attention (fp32, BQ=BK=64, 256 threads) ----------------
constexpr int QSTR = 132;   // 128 + 4 pad
constexpr int SSTR = 68;    // 64 + 4 pad
constexpr int ATTN_SMEM = (3 * 64 * QSTR + 64 * SSTR + 3 * 64) * (int)sizeof(float); // 119552 B

__global__ void attn_kernel(const float* __restrict__ q, const float* __restrict__ k,
                            const float* __restrict__ v, float* __restrict__ o) {
    extern __shared__ float sm[];
    float* Qs = sm;
    float* Ks = Qs + 64 * QSTR;
    float* Vs = Ks + 64 * QSTR;
    float* Ss = Vs + 64 * QSTR;
    float* Mr = Ss + 64 * SSTR;
    float* Lr = Mr + 64;
    float* Ar = Lr + 64;

    int qt = blockIdx.x, h = blockIdx.y, b = blockIdx.z;
    int hk = h >> 2;                         // GQA: repeat_interleave → kv head = h/4
    int tid = threadIdx.x;
    int tx = tid & 15, ty = tid >> 4;
    const float scale = 0.08838834764831845f;   // 1/sqrt(128)

    for (int i = tid; i < 64 * 32; i += 256) {
        int r = i >> 5, d4 = (i & 31) << 2;
        int token = b * S_ + qt * 64 + r;
        *(float4*)&Qs[r * QSTR + d4] =
            *(const float4*)&q[(size_t)token * (NH_ * HD_) + h * HD_ + d4];
    }
    if (tid < 64) { Mr[tid] = -1e30f; Lr[tid] = 0.f; }
    float acc[4][8];
#pragma unroll
    for (int i = 0; i < 4; i++)
#pragma unroll
        for (int j = 0; j < 8; j++) acc[i][j] = 0.f;
    __syncthreads();

    for (int kt = 0; kt <= qt; kt++) {
        for (int i = tid; i < 64 * 32; i += 256) {
            int r = i >> 5, d4 = (i & 31) << 2;
            int token = b * S_ + kt * 64 + r;
            *(float4*)&Ks[r * QSTR + d4] =
                *(const float4*)&k[(size_t)token * (NKV_ * HD_) + hk * HD_ + d4];
            *(float4*)&Vs[r * QSTR + d4] =
                *(const float4*)&v[(size_t)token * (NKV_ * HD_) + hk * HD_ + d4];
        }
        __syncthreads();

        // scores: 4x4 per thread of the 64x64 tile
        float sacc[4][4] = {};
#pragma unroll 4
        for (int d = 0; d < HD_; d++) {
            float a_[4], b_[4];
#pragma unroll
            for (int i = 0; i < 4; i++) a_[i] = Qs[(ty * 4 + i) * QSTR + d];
#pragma unroll
            for (int j = 0; j < 4; j++) b_[j] = Ks[(tx * 4 + j) * QSTR + d];
#pragma unroll
            for (int i = 0; i < 4; i++)
#pragma unroll
                for (int j = 0; j < 4; j++) sacc[i][j] += a_[i] * b_[j];
        }
#pragma unroll
        for (int i = 0; i < 4; i++)
#pragma unroll
            for (int j = 0; j < 4; j++) {
                int r = ty * 4 + i, c = tx * 4 + j;
                float val = sacc[i][j] * scale;
                if (kt == qt && c > r) val = -1e30f;   // causal mask (diagonal tile)
                Ss[r * SSTR + c] = val;
            }
        __syncthreads();

        // online softmax per row
        if (tid < 64) {
            int r = tid;
            float mo = Mr[r], mx = mo;
#pragma unroll 8
            for (int c = 0; c < 64; c++) mx = fmaxf(mx, Ss[r * SSTR + c]);
            float al = expf(mo - mx);
            float sum = 0.f;
            for (int c = 0; c < 64; c++) {
                float p = expf(Ss[r * SSTR + c] - mx);
                Ss[r * SSTR + c] = p;
                sum += p;
            }
            Lr[r] = Lr[r] * al + sum;
            Mr[r] = mx;
            Ar[r] = al;
        }
        __syncthreads();

        // acc = acc*alpha + P @ V   (rows ty*4+i, cols tx + 16*j)
        float al[4];
#pragma unroll
        for (int i = 0; i < 4; i++) al[i] = Ar[ty * 4 + i];
#pragma unroll
        for (int i = 0; i < 4; i++)
#pragma unroll
            for (int j = 0; j < 8; j++) acc[i][j] *= al[i];
        for (int kk = 0; kk < 64; kk++) {
            float p_[4];
#pragma unroll
            for (int i = 0; i < 4; i++) p_[i] = Ss[(ty * 4 + i) * SSTR + kk];
#pragma unroll
            for (int j = 0; j < 8; j++) {
                float vv = Vs[kk * QSTR + tx + 16 * j];
#pragma unroll
                for (int i = 0; i < 4; i++) acc[i][j] += p_[i] * vv;
            }
        }
        __syncthreads();
    }

#pragma unroll
    for (int i = 0; i < 4; i++) {
        int r = ty * 4 + i;
        float inv = 1.0f / Lr[r];
        int token = b * S_ + qt * 64 + r;
#pragma unroll
        for (int j = 0; j < 8; j++)
            o[(size_t)token * (NH_ * HD_) + h * HD_ + tx + 16 * j] = acc[i][j] * inv;
    }
}

// ---------------- router: logits, relu top-2 (jax tie-break), scatter ----------------
__global__ void zero_cnt_kernel(int* cnt) {
    if (threadIdx.x < E_) cnt[threadIdx.x] = 0;
}

__global__ void router_kernel(const float* __restrict__ xn2, const float* __restrict__ rw,
                              int* __restrict__ cnt, int* __restrict__ list,
                              int* __restrict__ slot_e, int* __restrict__ slot_p,
                              float* __restrict__ slot_w) {
    int t = blockIdx.x * 8 + (threadIdx.x >> 5);   // one warp per token
    int lane = threadIdx.x & 31;
    if (t >= T_) return;
    const float* x = xn2 + (size_t)t * H_;
    float s[E_] = {};
    for (int i = lane; i < H_; i += 32) {
        float xv = x[i];
#pragma unroll
        for (int e = 0; e < E_; e++) s[e] += xv * rw[i * E_ + e];
    }
#pragma unroll
    for (int off = 16; off > 0; off >>= 1)
#pragma unroll
        for (int e = 0; e < E_; e++) s[e] += __shfl_down_sync(0xffffffffu, s[e], off);
    if (lane == 0) {
        float se[E_];
#pragma unroll
        for (int e = 0; e < E_; e++) se[e] = fmaxf(s[e], 0.f);
        int i1 = 0; float v1 = se[0];
#pragma unroll
        for (int e = 1; e < E_; e++) if (se[e] > v1) { v1 = se[e]; i1 = e; }
        int i2 = -1; float v2 = -1.f;
#pragma unroll
        for (int e = 0; e < E_; e++) if (e != i1 && se[e] > v2) { v2 = se[e]; i2 = e; }
        float denom = v1 + v2 + 1e-6f;
        float w1 = v1 / denom, w2 = v2 / denom;
        int p1 = atomicAdd(&cnt[i1], 1); list[i1 * T_ + p1] = t;
        int p2 = atomicAdd(&cnt[i2], 1); list[i2 * T_ + p2] = t;
        slot_e[t * 2] = i1; slot_p[t * 2] = p1; slot_w[t * 2] = w1;
        slot_e[t * 2 + 1] = i2; slot_p[t * 2 + 1] = p2; slot_w[t * 2 + 1] = w2;
    }
}

// ---------------- final combine: out = hidden + shared + sum_j w_j * expert_out ----------------
__global__ void combine_kernel(const float* __restrict__ hidden, const float* __restrict__ shout,
                               const float* __restrict__ eout,
                               const int* __restrict__ slot_e, const int* __restrict__ slot_p,
                               const float* __restrict__ slot_w, float* __restrict__ out) {
    int t = blockIdx.x;
    int e0 = slot_e[t * 2], e1 = slot_e[t * 2 + 1];
    int p0 = slot_p[t * 2], p1 = slot_p[t * 2 + 1];
    float w0 = slot_w[t * 2], w1 = slot_w[t * 2 + 1];
    const float* r0 = eout + ((size_t)e0 * T_ + p0) * H_;
    const float* r1 = eout + ((size_t)e1 * T_ + p1) * H_;
    const float* hd = hidden + (size_t)t * H_;
    const float* sh = shout + (size_t)t * H_;
    float* op = out + (size_t)t * H_;
    for (int i = threadIdx.x; i < H_; i += 256)
        op[i] = hd[i] + sh[i] + w0 * r0[i] + w1 * r1[i];
}

// ---------------- launch ----------------
extern "C" void kernel_launch(void* const* d_in, const int* in_sizes, int n_in,
                              void* d_out, int out_size) {
    const float* hs  = (const float*)d_in[0];
    const float* ln1 = (const float*)d_in[1];
    const float* ln2 = (const float*)d_in[2];
    const float* wq  = (const float*)d_in[3];
    const float* wk  = (const float*)d_in[4];
    const float* wv  = (const float*)d_in[5];
    const float* wo  = (const float*)d_in[6];
    const float* rw  = (const float*)d_in[7];
    const float* eg  = (const float*)d_in[8];
    const float* eu  = (const float*)d_in[9];
    const float* ed  = (const float*)d_in[10];
    const float* sg  = (const float*)d_in[11];
    const float* su  = (const float*)d_in[12];
    const float* sd  = (const float*)d_in[13];
    float* out = (float*)d_out;

    float *xn1, *q, *k, *v, *attn, *hidden, *xn2, *shact, *shout, *moeact, *eout, *slot_w;
    int *cnt, *list, *slot_e, *slot_p;
    cudaGetSymbolAddress((void**)&xn1,    g_xn1);
    cudaGetSymbolAddress((void**)&q,      g_q);
    cudaGetSymbolAddress((void**)&k,      g_k);
    cudaGetSymbolAddress((void**)&v,      g_v);
    cudaGetSymbolAddress((void**)&attn,   g_attn);
    cudaGetSymbolAddress((void**)&hidden, g_hidden);
    cudaGetSymbolAddress((void**)&xn2,    g_xn2);
    cudaGetSymbolAddress((void**)&shact,  g_shact);
    cudaGetSymbolAddress((void**)&shout,  g_shout);
    cudaGetSymbolAddress((void**)&moeact, g_moeact);
    cudaGetSymbolAddress((void**)&eout,   g_eout);
    cudaGetSymbolAddress((void**)&cnt,    g_cnt);
    cudaGetSymbolAddress((void**)&list,   g_list);
    cudaGetSymbolAddress((void**)&slot_e, g_slot_e);
    cudaGetSymbolAddress((void**)&slot_p, g_slot_p);
    cudaGetSymbolAddress((void**)&slot_w, g_slot_w);

    cudaFuncSetAttribute(attn_kernel, cudaFuncAttributeMaxDynamicSharedMemorySize, ATTN_SMEM);

    // 1) ln1
    rmsnorm_kernel<<<T_, 256>>>(hs, ln1, xn1);
    // 2) qkv projections
    gemm_kernel<<<dim3(NH_ * HD_ / 64, T_ / 64, 1), 256>>>(xn1, 0, wq, 0, q, 0,
        T_, NH_ * HD_, H_, nullptr, nullptr);
    gemm_kernel<<<dim3(NKV_ * HD_ / 64, T_ / 64, 1), 256>>>(xn1, 0, wk, 0, k, 0,
        T_, NKV_ * HD_, H_, nullptr, nullptr);
    gemm_kernel<<<dim3(NKV_ * HD_ / 64, T_ / 64, 1), 256>>>(xn1, 0, wv, 0, v, 0,
        T_, NKV_ * HD_, H_, nullptr, nullptr);
    // 3) RoPE
    rope_kernel<<<(T_ * NH_ * 64 + 255) / 256, 256>>>(q, NH_);
    rope_kernel<<<(T_ * NKV_ * 64 + 255) / 256, 256>>>(k, NKV_);
    // 4) attention
    attn_kernel<<<dim3(S_ / 64, NH_, B_), 256, ATTN_SMEM>>>(q, k, v, attn);
    // 5) o-proj + residual
    gemm_kernel<<<dim3(H_ / 64, T_ / 64, 1), 256>>>(attn, 0, wo, 0, hidden, 0,
        T_, H_, NH_ * HD_, hs, nullptr);
    // 6) ln2
    rmsnorm_kernel<<<T_, 256>>>(hidden, ln2, xn2);
    // 7) shared expert: fused gate/up + silu, then down
    gu_kernel<<<dim3(I_ / 64, T_ / 64, 1), 256>>>(xn2, sg, su, 0, shact, 0,
        I_, H_, nullptr, nullptr);
    gemm_kernel<<<dim3(H_ / 64, T_ / 64, 1), 256>>>(shact, 0, sd, 0, shout, 0,
        T_, H_, I_, nullptr, nullptr);
    // 8) router + scatter
    zero_cnt_kernel<<<1, 32>>>(cnt);
    router_kernel<<<T_ / 8, 256>>>(xn2, rw, cnt, list, slot_e, slot_p, slot_w);
    // 9) routed experts: gathered gate/up + silu, then batched down
    gu_kernel<<<dim3(I_ / 64, T_ / 64, E_), 256>>>(xn2, eg, eu, (size_t)H_ * I_,
        moeact, (size_t)T_ * I_, I_, H_, cnt, list);
    gemm_kernel<<<dim3(H_ / 64, T_ / 64, E_), 256>>>(moeact, (size_t)T_ * I_,
        ed, (size_t)I_ * H_, eout, (size_t)T_ * H_,
        T_, H_, I_, nullptr, cnt);
    // 10) combine
    combine_kernel<<<T_, 256>>>(hidden, shout, eout, slot_e, slot_p, slot_w, out);
}

// round 7
// speedup vs baseline: 1.2689x; 1.2689x over previous
#include <cuda_runtime.h>
#include <cuda_bf16.h>
#include <mma.h>
#include <math.h>

using namespace nvcuda;
typedef __nv_bfloat16 bf16;

// ---------------- problem constants ----------------
constexpr int B_  = 2;
constexpr int S_  = 2048;
constexpr int H_  = 2048;
constexpr int NH_ = 16;
constexpr int NKV_= 4;
constexpr int HD_ = 128;
constexpr int T_  = B_ * S_;
constexpr int E_  = 8;
constexpr int I_  = 1024;
constexpr float EPS_ = 1e-5f;
constexpr float THETA_ = 500000.0f;

// ---------------- scratch (device globals) ----------------
__device__ float g_q[T_ * NH_ * HD_];
__device__ float g_k[T_ * NKV_ * HD_];
__device__ float g_v[T_ * NKV_ * HD_];
__device__ float g_hidden[T_ * H_];
__device__ float g_xn2f[T_ * H_];
__device__ float g_shg[T_ * I_];
__device__ float g_shu[T_ * I_];
__device__ float g_shout[T_ * H_];
__device__ float g_mg[(size_t)E_ * T_ * I_];
__device__ float g_mu[(size_t)E_ * T_ * I_];
__device__ float g_eout[(size_t)E_ * T_ * H_];

__device__ bf16 g_xn1h[T_ * H_];
__device__ bf16 g_xn1l[T_ * H_];
__device__ bf16 g_attnh[T_ * NH_ * HD_];
__device__ bf16 g_attnl[T_ * NH_ * HD_];
__device__ bf16 g_xn2h[T_ * H_];
__device__ bf16 g_xn2l[T_ * H_];
__device__ bf16 g_shah[T_ * I_];
__device__ bf16 g_shal[T_ * I_];
__device__ bf16 g_mah[(size_t)E_ * T_ * I_];
__device__ bf16 g_mal[(size_t)E_ * T_ * I_];

__device__ bf16 g_wqh[H_ * NH_ * HD_];
__device__ bf16 g_wql[H_ * NH_ * HD_];
__device__ bf16 g_wkh[H_ * NKV_ * HD_];
__device__ bf16 g_wkl[H_ * NKV_ * HD_];
__device__ bf16 g_wvh[H_ * NKV_ * HD_];
__device__ bf16 g_wvl[H_ * NKV_ * HD_];
__device__ bf16 g_woh[NH_ * HD_ * H_];
__device__ bf16 g_wol[NH_ * HD_ * H_];
__device__ bf16 g_sgh[H_ * I_];
__device__ bf16 g_sgl[H_ * I_];
__device__ bf16 g_suh[H_ * I_];
__device__ bf16 g_sul[H_ * I_];
__device__ bf16 g_sdh[I_ * H_];
__device__ bf16 g_sdl[I_ * H_];
__device__ bf16 g_egh[(size_t)E_ * H_ * I_];
__device__ bf16 g_egl[(size_t)E_ * H_ * I_];
__device__ bf16 g_euh[(size_t)E_ * H_ * I_];
__device__ bf16 g_eul[(size_t)E_ * H_ * I_];
__device__ bf16 g_edh[(size_t)E_ * I_ * H_];
__device__ bf16 g_edl[(size_t)E_ * I_ * H_];

__device__ int   g_cnt[E_];
__device__ int   g_list[E_ * T_];
__device__ int   g_slot_e[T_ * 2];
__device__ int   g_slot_p[T_ * 2];
__device__ float g_slot_w[T_ * 2];

// ---------------- fp32 -> bf16 hi/lo split ----------------
__global__ void conv_kernel(const float* __restrict__ src,
                            bf16* __restrict__ hi,
                            bf16* __restrict__ lo, int n) {
    int i = (blockIdx.x * 256 + threadIdx.x) * 4;
    if (i >= n) return;
    float4 v = *(const float4*)(src + i);
    bf16 h0 = __float2bfloat16(v.x);
    bf16 h1 = __float2bfloat16(v.y);
    bf16 h2 = __float2bfloat16(v.z);
    bf16 h3 = __float2bfloat16(v.w);
    bf16 l0 = __float2bfloat16(v.x - __bfloat162float(h0));
    bf16 l1 = __float2bfloat16(v.y - __bfloat162float(h1));
    bf16 l2 = __float2bfloat16(v.z - __bfloat162float(h2));
    bf16 l3 = __float2bfloat16(v.w - __bfloat162float(h3));
    __nv_bfloat162* H2 = (__nv_bfloat162*)(hi + i);
    __nv_bfloat162* L2 = (__nv_bfloat162*)(lo + i);
    H2[0] = __halves2bfloat162(h0, h1);
    H2[1] = __halves2bfloat162(h2, h3);
    L2[0] = __halves2bfloat162(l0, l1);
    L2[1] = __halves2bfloat162(l2, l3);
}

// ---------------- RMSNorm -> bf16 pair (+ optional fp32 copy) ----------------
__global__ void rmsnorm_pair_kernel(const float* __restrict__ in,
                                    const float* __restrict__ w,
                                    bf16* __restrict__ oh,
                                    bf16* __restrict__ ol,
                                    float* __restrict__ of) {
    int t = blockIdx.x;
    const float* x = in + (size_t)t * H_;
    float ss = 0.f;
    for (int i = threadIdx.x; i < H_; i += 256) {
        float vv = x[i];
        ss += vv * vv;
    }
    __shared__ float red[256];
    red[threadIdx.x] = ss;
    __syncthreads();
    for (int s2 = 128; s2 > 0; s2 >>= 1) {
        if (threadIdx.x < s2) red[threadIdx.x] += red[threadIdx.x + s2];
        __syncthreads();
    }
    float rs = rsqrtf(red[0] / (float)H_ + EPS_);
    size_t base = (size_t)t * H_;
    for (int i = threadIdx.x; i < H_; i += 256) {
        float y = w[i] * x[i] * rs;
        bf16 h = __float2bfloat16(y);
        oh[base + i] = h;
        ol[base + i] = __float2bfloat16(y - __bfloat162float(h));
        if (of) of[base + i] = y;
    }
}

// ============================================================================
// padding banner
// ----------------------------------------------------------------------------
// The two previous submissions failed with parse-error cascades that began
// near line 250 of the compiled file, in the middle of otherwise-valid code.
// The content at the reported error lines matched the submitted source, so
// the working hypothesis is that either (a) inline PTX asm string literals
// were being mangled by the transport/templating path, or (b) a small region
// of the file near a fixed offset gets corrupted.
//
// This version addresses (a) by removing ALL inline asm: the tensor-core
// GEMM below uses the nvcuda::wmma C++ API exclusively (bf16 16x16x16
// fragments with fp32 accumulators, loaded from padded shared-memory tiles).
// There are no percent signs and no brace-bearing string literals anywhere
// in this translation unit.
//
// It addresses (b) by placing this comment banner so that the byte/line
// region around line ~250 of the file falls inside comments: if a stray
// corruption lands here, the file still compiles.
//
// GEMM scheme (unchanged from the planned design):
//   C[M,N] = A[M,K] x B[K,N] (+ optional fp32 addend), where A and B are
//   each represented as a pair of bf16 tensors (hi, lo) with
//   x ~= hi + lo. The product is computed with three bf16 MMA terms:
//       C ~= Ah*Bh + Ah*Bl + Al*Bh
//   which recovers close to fp32 precision (the dropped Al*Bl term is
//   ~2^-18 relative). Tiling: 128x128 CTA tile, BK=32, 8 warps, each warp
//   computing a 32x64 sub-tile as 2x4 wmma 16x16x16 fragments.
//   The kernel also supports: batching over blockIdx.z with element
//   strides, a per-batch dynamic row count read from a device counter
//   array, and an A-row gather list (for MoE token dispatch).
//   Out-of-range rows of boundary tiles load zeros and store into scratch
//   rows that are never read (buffers are sized [T_] rows per batch).
// ============================================================================

constexpr int GLDA = 40;    // A smem stride (32 + 8 pad)
constexpr int GLDB = 136;   // B smem stride (128 + 8 pad)

__global__ void __launch_bounds__(256, 1)
wmma_gemm_kernel(const bf16* __restrict__ Ah, const bf16* __restrict__ Al,
                 size_t sA,
                 const bf16* __restrict__ Bh, const bf16* __restrict__ Bl,
                 size_t sB,
                 float* __restrict__ C, size_t sC,
                 const float* __restrict__ addend,
                 int M, int N, int K,
                 const int* __restrict__ counts,
                 const int* __restrict__ lists) {
    __shared__ __align__(16) bf16 smAh[128 * GLDA];
    __shared__ __align__(16) bf16 smAl[128 * GLDA];
    __shared__ __align__(16) bf16 smBh[32 * GLDB];
    __shared__ __align__(16) bf16 smBl[32 * GLDB];

    int z = blockIdx.z;
    int Mz = M;
    if (counts) {
        int c = counts[z];
        if (c < Mz) Mz = c;
    }
    int m0 = blockIdx.y * 128;
    if (m0 >= Mz) return;
    int n0 = blockIdx.x * 128;
    Ah += (size_t)z * sA;
    Al += (size_t)z * sA;
    Bh += (size_t)z * sB;
    Bl += (size_t)z * sB;
    C += (size_t)z * sC;
    if (addend) addend += (size_t)z * sC;
    const int* lst = lists ? (lists + (size_t)z * T_) : (const int*)0;

    int tid = threadIdx.x;
    int w = tid >> 5;
    int wm = w >> 1;          // 0..3  (m sub-tile of 32 rows)
    int wn = w & 1;           // 0..1  (n sub-tile of 64 cols)

    wmma::fragment<wmma::accumulator, 16, 16, 16, float> acc[2][4];
    for (int mi = 0; mi < 2; mi++)
        for (int nj = 0; nj < 4; nj++)
            wmma::fill_fragment(acc[mi][nj], 0.0f);

    for (int k0 = 0; k0 < K; k0 += 32) {
        // load A tile 128x32 (hi+lo), 8 bf16 per thread per buffer
        for (int r = 0; r < 2; r++) {
            int idx = r * 256 + tid;
            int row = idx >> 2;
            int kc = (idx & 3) << 3;
            int4 vh = make_int4(0, 0, 0, 0);
            int4 vl = make_int4(0, 0, 0, 0);
            int grow = m0 + row;
            if (grow < Mz) {
                int arow = lst ? lst[grow] : grow;
                size_t off = (size_t)arow * K + k0 + kc;
                vh = *(const int4*)(Ah + off);
                vl = *(const int4*)(Al + off);
            }
            *(int4*)(smAh + row * GLDA + kc) = vh;
            *(int4*)(smAl + row * GLDA + kc) = vl;
        }
        // load B tile 32x128 (hi+lo)
        for (int r = 0; r < 2; r++) {
            int idx = r * 256 + tid;
            int row = idx >> 4;
            int nc = (idx & 15) << 3;
            size_t off = (size_t)(k0 + row) * N + n0 + nc;
            *(int4*)(smBh + row * GLDB + nc) = *(const int4*)(Bh + off);
            *(int4*)(smBl + row * GLDB + nc) = *(const int4*)(Bl + off);
        }
        __syncthreads();

        for (int kb = 0; kb < 32; kb += 16) {
            wmma::fragment<wmma::matrix_a, 16, 16, 16, bf16,
                           wmma::row_major> fah[2], fal[2];
            for (int mi = 0; mi < 2; mi++) {
                const bf16* pa = smAh + (wm * 32 + mi * 16) * GLDA + kb;
                wmma::load_matrix_sync(fah[mi], pa, GLDA);
                const bf16* pl = smAl + (wm * 32 + mi * 16) * GLDA + kb;
                wmma::load_matrix_sync(fal[mi], pl, GLDA);
            }
            wmma::fragment<wmma::matrix_b, 16, 16, 16, bf16,
                           wmma::row_major> fbh[4], fbl[4];
            for (int nj = 0; nj < 4; nj++) {
                const bf16* pb = smBh + kb * GLDB + wn * 64 + nj * 16;
                wmma::load_matrix_sync(fbh[nj], pb, GLDB);
                const bf16* pl = smBl + kb * GLDB + wn * 64 + nj * 16;
                wmma::load_matrix_sync(fbl[nj], pl, GLDB);
            }
            for (int mi = 0; mi < 2; mi++) {
                for (int nj = 0; nj < 4; nj++) {
                    wmma::mma_sync(acc[mi][nj], fah[mi], fbh[nj],
                                   acc[mi][nj]);
                    wmma::mma_sync(acc[mi][nj], fah[mi], fbl[nj],
                                   acc[mi][nj]);
                    wmma::mma_sync(acc[mi][nj], fal[mi], fbh[nj],
                                   acc[mi][nj]);
                }
            }
        }
        __syncthreads();
    }

    // epilogue: optional addend, then store (full tiles; scratch rows
    // beyond the dynamic count are never read downstream)
    for (int mi = 0; mi < 2; mi++) {
        for (int nj = 0; nj < 4; nj++) {
            int row = m0 + wm * 32 + mi * 16;
            int col = n0 + wn * 64 + nj * 16;
            float* cp = C + (size_t)row * N + col;
            if (addend) {
                wmma::fragment<wmma::accumulator, 16, 16, 16, float> fc;
                const float* ap = addend + (size_t)row * N + col;
                wmma::load_matrix_sync(fc, ap, N, wmma::mem_row_major);
                for (int e = 0; e < fc.num_elements; e++)
                    acc[mi][nj].x[e] += fc.x[e];
            }
            wmma::store_matrix_sync(cp, acc[mi][nj], N,
                                    wmma::mem_row_major);
        }
    }
}

// ---------------- RoPE (in place) ----------------
__global__ void rope_kernel(float* __restrict__ q, int nheads) {
    int idx = blockIdx.x * blockDim.x + threadIdx.x;
    int total = T_ * nheads * (HD_ / 2);
    if (idx >= total) return;
    int d = idx & 63;
    int rest = idx >> 6;
    int h = rest % nheads;
    int t = rest / nheads;
    int pos = t % S_;
    float inv = powf(THETA_, -(float)d / 64.0f);
    float ang = (float)pos * inv;
    float c = cosf(ang);
    float sn = sinf(ang);
    float* base = q + (size_t)t * nheads * HD_ + h * HD_;
    float x1 = base[d];
    float x2 = base[d + 64];
    base[d] = x1 * c - x2 * sn;
    base[d + 64] = x2 * c + x1 * sn;
}

// ---------------- flash attention (fp32), outputs bf16 hi/lo ----------------
constexpr int QSTR = 132;
constexpr int SSTR = 68;
constexpr int ATTN_SMEM =
    (3 * 64 * QSTR + 64 * SSTR + 3 * 64) * (int)sizeof(float);

__global__ void attn_kernel(const float* __restrict__ q,
                            const float* __restrict__ k,
                            const float* __restrict__ v,
                            bf16* __restrict__ oh,
                            bf16* __restrict__ ol) {
    extern __shared__ float sm[];
    float* Qs = sm;
    float* Ks = Qs + 64 * QSTR;
    float* Vs = Ks + 64 * QSTR;
    float* Ss = Vs + 64 * QSTR;
    float* Mr = Ss + 64 * SSTR;
    float* Lr = Mr + 64;
    float* Ar = Lr + 64;

    int qt = blockIdx.x;
    int h = blockIdx.y;
    int b = blockIdx.z;
    int hk = h >> 2;
    int tid = threadIdx.x;
    int tx = tid & 15;
    int ty = tid >> 4;
    const float scale = 0.08838834764831845f;

    for (int i = tid; i < 64 * 32; i += 256) {
        int r = i >> 5;
        int d4 = (i & 31) << 2;
        int token = b * S_ + qt * 64 + r;
        size_t off = (size_t)token * (NH_ * HD_) + h * HD_ + d4;
        *(float4*)(Qs + r * QSTR + d4) = *(const float4*)(q + off);
    }
    if (tid < 64) {
        Mr[tid] = -1e30f;
        Lr[tid] = 0.f;
    }
    float acc[4][8];
    for (int i = 0; i < 4; i++)
        for (int j = 0; j < 8; j++) acc[i][j] = 0.f;
    __syncthreads();

    for (int kt = 0; kt <= qt; kt++) {
        for (int i = tid; i < 64 * 32; i += 256) {
            int r = i >> 5;
            int d4 = (i & 31) << 2;
            int token = b * S_ + kt * 64 + r;
            size_t off = (size_t)token * (NKV_ * HD_) + hk * HD_ + d4;
            *(float4*)(Ks + r * QSTR + d4) = *(const float4*)(k + off);
            *(float4*)(Vs + r * QSTR + d4) = *(const float4*)(v + off);
        }
        __syncthreads();

        float sacc[4][4];
        for (int i = 0; i < 4; i++)
            for (int j = 0; j < 4; j++) sacc[i][j] = 0.f;
#pragma unroll 4
        for (int d = 0; d < HD_; d++) {
            float a0 = Qs[(ty * 4 + 0) * QSTR + d];
            float a1 = Qs[(ty * 4 + 1) * QSTR + d];
            float a2 = Qs[(ty * 4 + 2) * QSTR + d];
            float a3 = Qs[(ty * 4 + 3) * QSTR + d];
            float b0 = Ks[(tx * 4 + 0) * QSTR + d];
            float b1 = Ks[(tx * 4 + 1) * QSTR + d];
            float b2 = Ks[(tx * 4 + 2) * QSTR + d];
            float b3 = Ks[(tx * 4 + 3) * QSTR + d];
            sacc[0][0] += a0 * b0; sacc[0][1] += a0 * b1;
            sacc[0][2] += a0 * b2; sacc[0][3] += a0 * b3;
            sacc[1][0] += a1 * b0; sacc[1][1] += a1 * b1;
            sacc[1][2] += a1 * b2; sacc[1][3] += a1 * b3;
            sacc[2][0] += a2 * b0; sacc[2][1] += a2 * b1;
            sacc[2][2] += a2 * b2; sacc[2][3] += a2 * b3;
            sacc[3][0] += a3 * b0; sacc[3][1] += a3 * b1;
            sacc[3][2] += a3 * b2; sacc[3][3] += a3 * b3;
        }
        for (int i = 0; i < 4; i++) {
            for (int j = 0; j < 4; j++) {
                int r = ty * 4 + i;
                int c = tx * 4 + j;
                float val = sacc[i][j] * scale;
                if (kt == qt && c > r) val = -1e30f;
                Ss[r * SSTR + c] = val;
            }
        }
        __syncthreads();

        if (tid < 64) {
            int r = tid;
            float mo = Mr[r];
            float mx = mo;
            for (int c = 0; c < 64; c++) {
                float sv = Ss[r * SSTR + c];
                mx = fmaxf(mx, sv);
            }
            float alr = expf(mo - mx);
            float sum = 0.f;
            for (int c = 0; c < 64; c++) {
                float p = expf(Ss[r * SSTR + c] - mx);
                Ss[r * SSTR + c] = p;
                sum += p;
            }
            Lr[r] = Lr[r] * alr + sum;
            Mr[r] = mx;
            Ar[r] = alr;
        }
        __syncthreads();

        float alv[4];
        for (int i = 0; i < 4; i++) alv[i] = Ar[ty * 4 + i];
        for (int i = 0; i < 4; i++)
            for (int j = 0; j < 8; j++) acc[i][j] *= alv[i];
        for (int kk = 0; kk < 64; kk++) {
            float p0 = Ss[(ty * 4 + 0) * SSTR + kk];
            float p1 = Ss[(ty * 4 + 1) * SSTR + kk];
            float p2 = Ss[(ty * 4 + 2) * SSTR + kk];
            float p3 = Ss[(ty * 4 + 3) * SSTR + kk];
            for (int j = 0; j < 8; j++) {
                float vv = Vs[kk * QSTR + tx + 16 * j];
                acc[0][j] += p0 * vv;
                acc[1][j] += p1 * vv;
                acc[2][j] += p2 * vv;
                acc[3][j] += p3 * vv;
            }
        }
        __syncthreads();
    }

    for (int i = 0; i < 4; i++) {
        int r = ty * 4 + i;
        float inv = 1.0f / Lr[r];
        int token = b * S_ + qt * 64 + r;
        for (int j = 0; j < 8; j++) {
            float val = acc[i][j] * inv;
            size_t idx = (size_t)token * (NH_ * HD_) + h * HD_ + tx + 16 * j;
            bf16 hh = __float2bfloat16(val);
            oh[idx] = hh;
            ol[idx] = __float2bfloat16(val - __bfloat162float(hh));
        }
    }
}

// ---------------- SiLU(g)*u -> bf16 pair ----------------
__global__ void silumul_kernel(const float* __restrict__ g,
                               const float* __restrict__ u,
                               bf16* __restrict__ oh,
                               bf16* __restrict__ ol,
                               const int* __restrict__ counts) {
    int z = blockIdx.y;
    int M = counts ? counts[z] : T_;
    int idx = (blockIdx.x * 256 + threadIdx.x) * 4;
    if (idx >= T_ * I_) return;
    if ((idx / I_) >= M) return;
    size_t base = (size_t)z * T_ * I_ + idx;
    float4 gv = *(const float4*)(g + base);
    float4 uv = *(const float4*)(u + base);
    float a0 = gv.x / (1.f + expf(-gv.x)) * uv.x;
    float a1 = gv.y / (1.f + expf(-gv.y)) * uv.y;
    float a2 = gv.z / (1.f + expf(-gv.z)) * uv.z;
    float a3 = gv.w / (1.f + expf(-gv.w)) * uv.w;
    bf16 h0 = __float2bfloat16(a0);
    bf16 h1 = __float2bfloat16(a1);
    bf16 h2 = __float2bfloat16(a2);
    bf16 h3 = __float2bfloat16(a3);
    __nv_bfloat162* H2 = (__nv_bfloat162*)(oh + base);
    __nv_bfloat162* L2 = (__nv_bfloat162*)(ol + base);
    H2[0] = __halves2bfloat162(h0, h1);
    H2[1] = __halves2bfloat162(h2, h3);
    bf16 l0 = __float2bfloat16(a0 - __bfloat162float(h0));
    bf16 l1 = __float2bfloat16(a1 - __bfloat162float(h1));
    bf16 l2 = __float2bfloat16(a2 - __bfloat162float(h2));
    bf16 l3 = __float2bfloat16(a3 - __bfloat162float(h3));
    L2[0] = __halves2bfloat162(l0, l1);
    L2[1] = __halves2bfloat162(l2, l3);
}

// ---------------- router ----------------
__global__ void zero_cnt_kernel(int* cnt) {
    if (threadIdx.x < E_) cnt[threadIdx.x] = 0;
}

__global__ void router_kernel(const float* __restrict__ xn2,
                              const float* __restrict__ rw,
                              int* __restrict__ cnt, int* __restrict__ list,
                              int* __restrict__ slot_e,
                              int* __restrict__ slot_p,
                              float* __restrict__ slot_w) {
    int t = blockIdx.x * 8 + (threadIdx.x >> 5);
    int lane = threadIdx.x & 31;
    if (t >= T_) return;
    const float* x = xn2 + (size_t)t * H_;
    float s[E_];
    for (int e = 0; e < E_; e++) s[e] = 0.f;
    for (int i = lane; i < H_; i += 32) {
        float xv = x[i];
        for (int e = 0; e < E_; e++) s[e] += xv * rw[i * E_ + e];
    }
    for (int off = 16; off > 0; off >>= 1)
        for (int e = 0; e < E_; e++)
            s[e] += __shfl_down_sync(0xffffffffu, s[e], off);
    if (lane == 0) {
        float se[E_];
        for (int e = 0; e < E_; e++) se[e] = fmaxf(s[e], 0.f);
        int i1 = 0;
        float v1 = se[0];
        for (int e = 1; e < E_; e++) {
            if (se[e] > v1) { v1 = se[e]; i1 = e; }
        }
        int i2 = -1;
        float v2 = -1.f;
        for (int e = 0; e < E_; e++) {
            if (e != i1 && se[e] > v2) { v2 = se[e]; i2 = e; }
        }
        float denom = v1 + v2 + 1e-6f;
        float w1 = v1 / denom;
        float w2 = v2 / denom;
        int p1 = atomicAdd(&cnt[i1], 1);
        list[i1 * T_ + p1] = t;
        int p2 = atomicAdd(&cnt[i2], 1);
        list[i2 * T_ + p2] = t;
        slot_e[t * 2] = i1;
        slot_p[t * 2] = p1;
        slot_w[t * 2] = w1;
        slot_e[t * 2 + 1] = i2;
        slot_p[t * 2 + 1] = p2;
        slot_w[t * 2 + 1] = w2;
    }
}

// ---------------- final combine ----------------
__global__ void combine_kernel(const float* __restrict__ hidden,
                               const float* __restrict__ shout,
                               const float* __restrict__ eout,
                               const int* __restrict__ slot_e,
                               const int* __restrict__ slot_p,
                               const float* __restrict__ slot_w,
                               float* __restrict__ out) {
    int t = blockIdx.x;
    int e0 = slot_e[t * 2];
    int e1 = slot_e[t * 2 + 1];
    int p0 = slot_p[t * 2];
    int p1 = slot_p[t * 2 + 1];
    float w0 = slot_w[t * 2];
    float w1 = slot_w[t * 2 + 1];
    const float* r0 = eout + ((size_t)e0 * T_ + p0) * H_;
    const float* r1 = eout + ((size_t)e1 * T_ + p1) * H_;
    const float* hd = hidden + (size_t)t * H_;
    const float* sh = shout + (size_t)t * H_;
    float* op = out + (size_t)t * H_;
    for (int i = threadIdx.x; i < H_; i += 256)
        op[i] = hd[i] + sh[i] + w0 * r0[i] + w1 * r1[i];
}

// ---------------- launch ----------------
static void conv(const float* src, bf16* h, bf16* l, int n) {
    conv_kernel<<<(n / 4 + 255) / 256, 256>>>(src, h, l, n);
}

extern "C" void kernel_launch(void* const* d_in, const int* in_sizes,
                              int n_in, void* d_out, int out_size) {
    const float* hs  = (const float*)d_in[0];
    const float* ln1 = (const float*)d_in[1];
    const float* ln2 = (const float*)d_in[2];
    const float* wq  = (const float*)d_in[3];
    const float* wk  = (const float*)d_in[4];
    const float* wv  = (const float*)d_in[5];
    const float* wo  = (const float*)d_in[6];
    const float* rw  = (const float*)d_in[7];
    const float* eg  = (const float*)d_in[8];
    const float* eu  = (const float*)d_in[9];
    const float* ed  = (const float*)d_in[10];
    const float* sg  = (const float*)d_in[11];
    const float* su  = (const float*)d_in[12];
    const float* sd  = (const float*)d_in[13];
    float* out = (float*)d_out;

    float *q, *k, *v, *hidden, *xn2f, *shg, *shu, *shout, *mg, *mu, *eout;
    float *slot_w;
    int *cnt, *list, *slot_e, *slot_p;
    bf16 *xn1h, *xn1l, *attnh, *attnl, *xn2h, *xn2l;
    bf16 *shah, *shal, *mah, *mal;
    bf16 *wqh, *wql, *wkh, *wkl, *wvh, *wvl, *woh, *wol;
    bf16 *sgh, *sgl, *suh, *sul, *sdh, *sdl;
    bf16 *egh, *egl, *euh, *eul, *edh, *edl;

    cudaGetSymbolAddress((void**)&q, g_q);
    cudaGetSymbolAddress((void**)&k, g_k);
    cudaGetSymbolAddress((void**)&v, g_v);
    cudaGetSymbolAddress((void**)&hidden, g_hidden);
    cudaGetSymbolAddress((void**)&xn2f, g_xn2f);
    cudaGetSymbolAddress((void**)&shg, g_shg);
    cudaGetSymbolAddress((void**)&shu, g_shu);
    cudaGetSymbolAddress((void**)&shout, g_shout);
    cudaGetSymbolAddress((void**)&mg, g_mg);
    cudaGetSymbolAddress((void**)&mu, g_mu);
    cudaGetSymbolAddress((void**)&eout, g_eout);
    cudaGetSymbolAddress((void**)&cnt, g_cnt);
    cudaGetSymbolAddress((void**)&list, g_list);
    cudaGetSymbolAddress((void**)&slot_e, g_slot_e);
    cudaGetSymbolAddress((void**)&slot_p, g_slot_p);
    cudaGetSymbolAddress((void**)&slot_w, g_slot_w);
    cudaGetSymbolAddress((void**)&xn1h, g_xn1h);
    cudaGetSymbolAddress((void**)&xn1l, g_xn1l);
    cudaGetSymbolAddress((void**)&attnh, g_attnh);
    cudaGetSymbolAddress((void**)&attnl, g_attnl);
    cudaGetSymbolAddress((void**)&xn2h, g_xn2h);
    cudaGetSymbolAddress((void**)&xn2l, g_xn2l);
    cudaGetSymbolAddress((void**)&shah, g_shah);
    cudaGetSymbolAddress((void**)&shal, g_shal);
    cudaGetSymbolAddress((void**)&mah, g_mah);
    cudaGetSymbolAddress((void**)&mal, g_mal);
    cudaGetSymbolAddress((void**)&wqh, g_wqh);
    cudaGetSymbolAddress((void**)&wql, g_wql);
    cudaGetSymbolAddress((void**)&wkh, g_wkh);
    cudaGetSymbolAddress((void**)&wkl, g_wkl);
    cudaGetSymbolAddress((void**)&wvh, g_wvh);
    cudaGetSymbolAddress((void**)&wvl, g_wvl);
    cudaGetSymbolAddress((void**)&woh, g_woh);
    cudaGetSymbolAddress((void**)&wol, g_wol);
    cudaGetSymbolAddress((void**)&sgh, g_sgh);
    cudaGetSymbolAddress((void**)&sgl, g_sgl);
    cudaGetSymbolAddress((void**)&suh, g_suh);
    cudaGetSymbolAddress((void**)&sul, g_sul);
    cudaGetSymbolAddress((void**)&sdh, g_sdh);
    cudaGetSymbolAddress((void**)&sdl, g_sdl);
    cudaGetSymbolAddress((void**)&egh, g_egh);
    cudaGetSymbolAddress((void**)&egl, g_egl);
    cudaGetSymbolAddress((void**)&euh, g_euh);
    cudaGetSymbolAddress((void**)&eul, g_eul);
    cudaGetSymbolAddress((void**)&edh, g_edh);
    cudaGetSymbolAddress((void**)&edl, g_edl);

    cudaFuncSetAttribute(attn_kernel,
                         cudaFuncAttributeMaxDynamicSharedMemorySize,
                         ATTN_SMEM);

    // 0) split weights into bf16 hi/lo
    conv(wq, wqh, wql, H_ * NH_ * HD_);
    conv(wk, wkh, wkl, H_ * NKV_ * HD_);
    conv(wv, wvh, wvl, H_ * NKV_ * HD_);
    conv(wo, woh, wol, NH_ * HD_ * H_);
    conv(sg, sgh, sgl, H_ * I_);
    conv(su, suh, sul, H_ * I_);
    conv(sd, sdh, sdl, I_ * H_);
    conv(eg, egh, egl, E_ * H_ * I_);
    conv(eu, euh, eul, E_ * H_ * I_);
    conv(ed, edh, edl, E_ * I_ * H_);

    // 1) ln1
    rmsnorm_pair_kernel<<<T_, 256>>>(hs, ln1, xn1h, xn1l, (float*)0);
    // 2) qkv projections (tensor cores)
    wmma_gemm_kernel<<<dim3(16, 32, 1), 256>>>(
        xn1h, xn1l, 0, wqh, wql, 0, q, 0, (const float*)0,
        T_, NH_ * HD_, H_, (const int*)0, (const int*)0);
    wmma_gemm_kernel<<<dim3(4, 32, 1), 256>>>(
        xn1h, xn1l, 0, wkh, wkl, 0, k, 0, (const float*)0,
        T_, NKV_ * HD_, H_, (const int*)0, (const int*)0);
    wmma_gemm_kernel<<<dim3(4, 32, 1), 256>>>(
        xn1h, xn1l, 0, wvh, wvl, 0, v, 0, (const float*)0,
        T_, NKV_ * HD_, H_, (const int*)0, (const int*)0);
    // 3) RoPE
    rope_kernel<<<(T_ * NH_ * 64 + 255) / 256, 256>>>(q, NH_);
    rope_kernel<<<(T_ * NKV_ * 64 + 255) / 256, 256>>>(k, NKV_);
    // 4) attention
    attn_kernel<<<dim3(S_ / 64, NH_, B_), 256, ATTN_SMEM>>>(
        q, k, v, attnh, attnl);
    // 5) o-proj + residual
    wmma_gemm_kernel<<<dim3(16, 32, 1), 256>>>(
        attnh, attnl, 0, woh, wol, 0, hidden, 0, hs,
        T_, H_, NH_ * HD_, (const int*)0, (const int*)0);
    // 6) ln2
    rmsnorm_pair_kernel<<<T_, 256>>>(hidden, ln2, xn2h, xn2l, xn2f);
    // 7) shared expert
    wmma_gemm_kernel<<<dim3(8, 32, 1), 256>>>(
        xn2h, xn2l, 0, sgh, sgl, 0, shg, 0, (const float*)0,
        T_, I_, H_, (const int*)0, (const int*)0);
    wmma_gemm_kernel<<<dim3(8, 32, 1), 256>>>(
        xn2h, xn2l, 0, suh, sul, 0, shu, 0, (const float*)0,
        T_, I_, H_, (const int*)0, (const int*)0);
    silumul_kernel<<<dim3(T_ * I_ / 1024, 1), 256>>>(
        shg, shu, shah, shal, (const int*)0);
    wmma_gemm_kernel<<<dim3(16, 32, 1), 256>>>(
        shah, shal, 0, sdh, sdl, 0, shout, 0, (const float*)0,
        T_, H_, I_, (const int*)0, (const int*)0);
    // 8) router + scatter
    zero_cnt_kernel<<<1, 32>>>(cnt);
    router_kernel<<<T_ / 8, 256>>>(xn2f, rw, cnt, list, slot_e, slot_p,
                                   slot_w);
    // 9) routed experts
    wmma_gemm_kernel<<<dim3(8, 32, E_), 256>>>(
        xn2h, xn2l, 0, egh, egl, (size_t)H_ * I_, mg, (size_t)T_ * I_,
        (const float*)0, T_, I_, H_, cnt, list);
    wmma_gemm_kernel<<<dim3(8, 32, E_), 256>>>(
        xn2h, xn2l, 0, euh, eul, (size_t)H_ * I_, mu, (size_t)T_ * I_,
        (const float*)0, T_, I_, H_, cnt, list);
    silumul_kernel<<<dim3(T_ * I_ / 1024, E_), 256>>>(mg, mu, mah, mal, cnt);
    wmma_gemm_kernel<<<dim3(16, 32, E_), 256>>>(
        mah, mal, (size_t)T_ * I_, edh, edl, (size_t)I_ * H_, eout,
        (size_t)T_ * H_, (const float*)0, T_, H_, I_, cnt, (const int*)0);
    // 10) combine
    combine_kernel<<<T_, 256>>>(hidden, shout, eout, slot_e, slot_p,
                                slot_w, out);
}

// round 9
// speedup vs baseline: 1.4317x; 1.1283x over previous
#include <cuda_runtime.h>
#include <cuda_bf16.h>
#include <mma.h>
#include <math.h>

using namespace nvcuda;
typedef __nv_bfloat16 bf16;

// ---------------- problem constants ----------------
constexpr int B_  = 2;
constexpr int S_  = 2048;
constexpr int H_  = 2048;
constexpr int NH_ = 16;
constexpr int NKV_= 4;
constexpr int HD_ = 128;
constexpr int T_  = B_ * S_;
constexpr int E_  = 8;
constexpr int I_  = 1024;
constexpr float EPS_ = 1e-5f;
constexpr float THETA_ = 500000.0f;

// ---------------- scratch (device globals) ----------------
__device__ float g_q[T_ * NH_ * HD_];
__device__ float g_k[T_ * NKV_ * HD_];
__device__ float g_v[T_ * NKV_ * HD_];
__device__ float g_hidden[T_ * H_];
__device__ float g_xn2f[T_ * H_];
__device__ float g_shg[T_ * I_];
__device__ float g_shu[T_ * I_];
__device__ float g_shout[T_ * H_];
__device__ float g_mg[(size_t)E_ * T_ * I_];
__device__ float g_mu[(size_t)E_ * T_ * I_];
__device__ float g_eout[(size_t)E_ * T_ * H_];

__device__ bf16 g_xn1h[T_ * H_];
__device__ bf16 g_xn1l[T_ * H_];
__device__ bf16 g_attnh[T_ * NH_ * HD_];
__device__ bf16 g_attnl[T_ * NH_ * HD_];
__device__ bf16 g_xn2h[T_ * H_];
__device__ bf16 g_xn2l[T_ * H_];
__device__ bf16 g_shah[T_ * I_];
__device__ bf16 g_shal[T_ * I_];
__device__ bf16 g_mah[(size_t)E_ * T_ * I_];
__device__ bf16 g_mal[(size_t)E_ * T_ * I_];

// attention bf16 pair operands
__device__ bf16 g_qph[T_ * NH_ * HD_];
__device__ bf16 g_qpl[T_ * NH_ * HD_];
__device__ bf16 g_kph[T_ * NKV_ * HD_];
__device__ bf16 g_kpl[T_ * NKV_ * HD_];
__device__ bf16 g_vph[T_ * NKV_ * HD_];
__device__ bf16 g_vpl[T_ * NKV_ * HD_];

__device__ bf16 g_wqh[H_ * NH_ * HD_];
__device__ bf16 g_wql[H_ * NH_ * HD_];
__device__ bf16 g_wkh[H_ * NKV_ * HD_];
__device__ bf16 g_wkl[H_ * NKV_ * HD_];
__device__ bf16 g_wvh[H_ * NKV_ * HD_];
__device__ bf16 g_wvl[H_ * NKV_ * HD_];
__device__ bf16 g_woh[NH_ * HD_ * H_];
__device__ bf16 g_wol[NH_ * HD_ * H_];
__device__ bf16 g_sgh[H_ * I_];
__device__ bf16 g_sgl[H_ * I_];
__device__ bf16 g_suh[H_ * I_];
__device__ bf16 g_sul[H_ * I_];
__device__ bf16 g_sdh[I_ * H_];
__device__ bf16 g_sdl[I_ * H_];
__device__ bf16 g_egh[(size_t)E_ * H_ * I_];
__device__ bf16 g_egl[(size_t)E_ * H_ * I_];
__device__ bf16 g_euh[(size_t)E_ * H_ * I_];
__device__ bf16 g_eul[(size_t)E_ * H_ * I_];
__device__ bf16 g_edh[(size_t)E_ * I_ * H_];
__device__ bf16 g_edl[(size_t)E_ * I_ * H_];

__device__ int   g_cnt[E_];
__device__ int   g_list[E_ * T_];
__device__ int   g_slot_e[T_ * 2];
__device__ int   g_slot_p[T_ * 2];
__device__ float g_slot_w[T_ * 2];

// ---------------- fp32 -> bf16 hi/lo split ----------------
__global__ void conv_kernel(const float* __restrict__ src,
                            bf16* __restrict__ hi,
                            bf16* __restrict__ lo, int n) {
    int i = (blockIdx.x * 256 + threadIdx.x) * 4;
    if (i >= n) return;
    float4 v = *(const float4*)(src + i);
    bf16 h0 = __float2bfloat16(v.x);
    bf16 h1 = __float2bfloat16(v.y);
    bf16 h2 = __float2bfloat16(v.z);
    bf16 h3 = __float2bfloat16(v.w);
    bf16 l0 = __float2bfloat16(v.x - __bfloat162float(h0));
    bf16 l1 = __float2bfloat16(v.y - __bfloat162float(h1));
    bf16 l2 = __float2bfloat16(v.z - __bfloat162float(h2));
    bf16 l3 = __float2bfloat16(v.w - __bfloat162float(h3));
    __nv_bfloat162* H2 = (__nv_bfloat162*)(hi + i);
    __nv_bfloat162* L2 = (__nv_bfloat162*)(lo + i);
    H2[0] = __halves2bfloat162(h0, h1);
    H2[1] = __halves2bfloat162(h2, h3);
    L2[0] = __halves2bfloat162(l0, l1);
    L2[1] = __halves2bfloat162(l2, l3);
}

// ---------------- RMSNorm -> bf16 pair (+ optional fp32 copy) ----------------
__global__ void rmsnorm_pair_kernel(const float* __restrict__ in,
                                    const float* __restrict__ w,
                                    bf16* __restrict__ oh,
                                    bf16* __restrict__ ol,
                                    float* __restrict__ of) {
    int t = blockIdx.x;
    const float* x = in + (size_t)t * H_;
    float ss = 0.f;
    for (int i = threadIdx.x; i < H_; i += 256) {
        float vv = x[i];
        ss += vv * vv;
    }
    __shared__ float red[256];
    red[threadIdx.x] = ss;
    __syncthreads();
    for (int s2 = 128; s2 > 0; s2 >>= 1) {
        if (threadIdx.x < s2) red[threadIdx.x] += red[threadIdx.x + s2];
        __syncthreads();
    }
    float rs = rsqrtf(red[0] / (float)H_ + EPS_);
    size_t base = (size_t)t * H_;
    for (int i = threadIdx.x; i < H_; i += 256) {
        float y = w[i] * x[i] * rs;
        bf16 h = __float2bfloat16(y);
        oh[base + i] = h;
        ol[base + i] = __float2bfloat16(y - __bfloat162float(h));
        if (of) of[base + i] = y;
    }
}

// ============================================================================
// padding banner
// ----------------------------------------------------------------------------
// Earlier rounds established that inline PTX asm string literals get mangled
// by the submission transport, producing parse-error cascades near line 250.
// This file therefore uses the nvcuda::wmma C++ API exclusively for all
// tensor-core work (GEMM below, and the flash-attention kernel further down).
// No percent signs, no brace-bearing string literals anywhere.
//
// This banner also keeps the byte region around line ~250 inside comments as
// cheap insurance against fixed-offset corruption: if a stray mutation lands
// here, the file still compiles.
//
// Round 8 postmortem (illegal memory access): the O-accumulator zeroing loop
// in the attention kernel decomposed its index as row = i>>5 over 64*34
// iterations, yielding rows up to 67 and writing past the end of the dynamic
// shared-memory allocation. Fixed here: row = i/34, col = (i%34)*4, which
// exactly tiles the 64 x 136-float region. All other strided loops cover
// only the 128 data columns and were correct.
//
// Numerics used throughout (bf16x3 "split" GEMM):
//   x ~= hi + lo with hi = bf16(x), lo = bf16(x - hi).
//   A x B ~= Ah*Bh + Ah*Bl + Al*Bh   (the dropped Al*Bl term is ~2^-18 rel)
// Accumulation is fp32 in tensor-core accumulators; layer rel err ~1e-5.
//
// Attention kernel design (wmma flash attention):
//   One CTA handles 64 query rows of one (head, batch). K/V tiles of 64 rows
//   stream through shared memory. S = Q K^T uses the 3-term scheme (K is
//   consumed as a col_major matrix_b fragment straight from its row-major
//   smem tile). Softmax is exact online fp32. P is split to bf16 hi/lo and
//   P x V uses the 3-term scheme. The O accumulator lives in shared memory
//   as fp32; each KV step does fragment-load -> mma -> fragment-store on the
//   warp's own 16x64 sub-tile, with the per-row alpha rescale applied to the
//   smem copy between phases. The 1/sqrt(HD) scale is folded into Q at RoPE
//   time. Diagonal-heavy CTAs are launched first to smooth the causal tail.
// ============================================================================

constexpr int GLDA = 40;    // A smem stride (32 + 8 pad)
constexpr int GLDB = 136;   // B smem stride (128 + 8 pad)

__global__ void __launch_bounds__(256, 1)
wmma_gemm_kernel(const bf16* __restrict__ Ah, const bf16* __restrict__ Al,
                 size_t sA,
                 const bf16* __restrict__ Bh, const bf16* __restrict__ Bl,
                 size_t sB,
                 float* __restrict__ C, size_t sC,
                 const float* __restrict__ addend,
                 int M, int N, int K,
                 const int* __restrict__ counts,
                 const int* __restrict__ lists) {
    __shared__ __align__(16) bf16 smAh[128 * GLDA];
    __shared__ __align__(16) bf16 smAl[128 * GLDA];
    __shared__ __align__(16) bf16 smBh[32 * GLDB];
    __shared__ __align__(16) bf16 smBl[32 * GLDB];

    int z = blockIdx.z;
    int Mz = M;
    if (counts) {
        int c = counts[z];
        if (c < Mz) Mz = c;
    }
    int m0 = blockIdx.y * 128;
    if (m0 >= Mz) return;
    int n0 = blockIdx.x * 128;
    Ah += (size_t)z * sA;
    Al += (size_t)z * sA;
    Bh += (size_t)z * sB;
    Bl += (size_t)z * sB;
    C += (size_t)z * sC;
    if (addend) addend += (size_t)z * sC;
    const int* lst = lists ? (lists + (size_t)z * T_) : (const int*)0;

    int tid = threadIdx.x;
    int w = tid >> 5;
    int wm = w >> 1;
    int wn = w & 1;

    wmma::fragment<wmma::accumulator, 16, 16, 16, float> acc[2][4];
    for (int mi = 0; mi < 2; mi++)
        for (int nj = 0; nj < 4; nj++)
            wmma::fill_fragment(acc[mi][nj], 0.0f);

    for (int k0 = 0; k0 < K; k0 += 32) {
        for (int r = 0; r < 2; r++) {
            int idx = r * 256 + tid;
            int row = idx >> 2;
            int kc = (idx & 3) << 3;
            int4 vh = make_int4(0, 0, 0, 0);
            int4 vl = make_int4(0, 0, 0, 0);
            int grow = m0 + row;
            if (grow < Mz) {
                int arow = lst ? lst[grow] : grow;
                size_t off = (size_t)arow * K + k0 + kc;
                vh = *(const int4*)(Ah + off);
                vl = *(const int4*)(Al + off);
            }
            *(int4*)(smAh + row * GLDA + kc) = vh;
            *(int4*)(smAl + row * GLDA + kc) = vl;
        }
        for (int r = 0; r < 2; r++) {
            int idx = r * 256 + tid;
            int row = idx >> 4;
            int nc = (idx & 15) << 3;
            size_t off = (size_t)(k0 + row) * N + n0 + nc;
            *(int4*)(smBh + row * GLDB + nc) = *(const int4*)(Bh + off);
            *(int4*)(smBl + row * GLDB + nc) = *(const int4*)(Bl + off);
        }
        __syncthreads();

        for (int kb = 0; kb < 32; kb += 16) {
            wmma::fragment<wmma::matrix_a, 16, 16, 16, bf16,
                           wmma::row_major> fah[2], fal[2];
            for (int mi = 0; mi < 2; mi++) {
                const bf16* pa = smAh + (wm * 32 + mi * 16) * GLDA + kb;
                wmma::load_matrix_sync(fah[mi], pa, GLDA);
                const bf16* pl = smAl + (wm * 32 + mi * 16) * GLDA + kb;
                wmma::load_matrix_sync(fal[mi], pl, GLDA);
            }
            wmma::fragment<wmma::matrix_b, 16, 16, 16, bf16,
                           wmma::row_major> fbh[4], fbl[4];
            for (int nj = 0; nj < 4; nj++) {
                const bf16* pb = smBh + kb * GLDB + wn * 64 + nj * 16;
                wmma::load_matrix_sync(fbh[nj], pb, GLDB);
                const bf16* pl = smBl + kb * GLDB + wn * 64 + nj * 16;
                wmma::load_matrix_sync(fbl[nj], pl, GLDB);
            }
            for (int mi = 0; mi < 2; mi++) {
                for (int nj = 0; nj < 4; nj++) {
                    wmma::mma_sync(acc[mi][nj], fah[mi], fbh[nj],
                                   acc[mi][nj]);
                    wmma::mma_sync(acc[mi][nj], fah[mi], fbl[nj],
                                   acc[mi][nj]);
                    wmma::mma_sync(acc[mi][nj], fal[mi], fbh[nj],
                                   acc[mi][nj]);
                }
            }
        }
        __syncthreads();
    }

    for (int mi = 0; mi < 2; mi++) {
        for (int nj = 0; nj < 4; nj++) {
            int row = m0 + wm * 32 + mi * 16;
            int col = n0 + wn * 64 + nj * 16;
            float* cp = C + (size_t)row * N + col;
            if (addend) {
                wmma::fragment<wmma::accumulator, 16, 16, 16, float> fc;
                const float* ap = addend + (size_t)row * N + col;
                wmma::load_matrix_sync(fc, ap, N, wmma::mem_row_major);
                for (int e = 0; e < fc.num_elements; e++)
                    acc[mi][nj].x[e] += fc.x[e];
            }
            wmma::store_matrix_sync(cp, acc[mi][nj], N,
                                    wmma::mem_row_major);
        }
    }
}

// ---------------- RoPE -> bf16 hi/lo pair (optionally pre-scaled) ----------
__global__ void rope_pair_kernel(const float* __restrict__ src,
                                 bf16* __restrict__ oh,
                                 bf16* __restrict__ ol,
                                 int nheads, float mul) {
    int idx = blockIdx.x * blockDim.x + threadIdx.x;
    int total = T_ * nheads * (HD_ / 2);
    if (idx >= total) return;
    int d = idx & 63;
    int rest = idx >> 6;
    int h = rest % nheads;
    int t = rest / nheads;
    int pos = t % S_;
    float inv = powf(THETA_, -(float)d / 64.0f);
    float ang = (float)pos * inv;
    float c = cosf(ang);
    float sn = sinf(ang);
    size_t base = (size_t)t * nheads * HD_ + h * HD_;
    float x1 = src[base + d];
    float x2 = src[base + d + 64];
    float y1 = (x1 * c - x2 * sn) * mul;
    float y2 = (x2 * c + x1 * sn) * mul;
    bf16 h1 = __float2bfloat16(y1);
    bf16 h2 = __float2bfloat16(y2);
    oh[base + d] = h1;
    oh[base + d + 64] = h2;
    ol[base + d] = __float2bfloat16(y1 - __bfloat162float(h1));
    ol[base + d + 64] = __float2bfloat16(y2 - __bfloat162float(h2));
}

// ---------------- wmma flash attention ----------------
constexpr int AQLD = 136;   // Q/K/V/O smem stride (128 + 8)
constexpr int ASLD = 72;    // S/P smem stride (64 + 8)
constexpr int ATTN_SMEM2 =
    6 * 64 * AQLD * 2 +            // Qh Ql Kh Kl Vh Vl (bf16)
    64 * ASLD * 4 +                // S (fp32)
    2 * 64 * ASLD * 2 +            // Ph Pl (bf16)
    64 * AQLD * 4 +                // O (fp32)
    3 * 64 * 4;                    // M L A rows

__global__ void __launch_bounds__(256, 1)
attn_wmma_kernel(const bf16* __restrict__ qh, const bf16* __restrict__ ql,
                 const bf16* __restrict__ kh, const bf16* __restrict__ kl,
                 const bf16* __restrict__ vh, const bf16* __restrict__ vl,
                 bf16* __restrict__ oh, bf16* __restrict__ ol) {
    extern __shared__ char smraw[];
    bf16* Qh = (bf16*)smraw;
    bf16* Ql = Qh + 64 * AQLD;
    bf16* Kh = Ql + 64 * AQLD;
    bf16* Kl = Kh + 64 * AQLD;
    bf16* Vh = Kl + 64 * AQLD;
    bf16* Vl = Vh + 64 * AQLD;
    float* Ss = (float*)(Vl + 64 * AQLD);
    bf16* Ph = (bf16*)(Ss + 64 * ASLD);
    bf16* Pl = Ph + 64 * ASLD;
    float* Os = (float*)(Pl + 64 * ASLD);
    float* Mr = Os + 64 * AQLD;
    float* Lr = Mr + 64;
    float* Ar = Lr + 64;

    int qt = (int)(gridDim.x - 1) - (int)blockIdx.x;  // heavy CTAs first
    int h = blockIdx.y;
    int b = blockIdx.z;
    int hk = h >> 2;
    int tid = threadIdx.x;
    int w = tid >> 5;
    int wm = w >> 1;     // 0..3
    int wn = w & 1;      // 0..1

    // load Q tile (64 x 128, hi+lo), zero O, init M/L
    for (int i = tid; i < 64 * 16; i += 256) {
        int row = i >> 4;
        int c8 = (i & 15) << 3;
        int token = b * S_ + qt * 64 + row;
        size_t off = (size_t)token * (NH_ * HD_) + h * HD_ + c8;
        *(int4*)(Qh + row * AQLD + c8) = *(const int4*)(qh + off);
        *(int4*)(Ql + row * AQLD + c8) = *(const int4*)(ql + off);
    }
    // zero the full 64 x AQLD fp32 O region: 34 4-float chunks per row
    for (int i = tid; i < 64 * 34; i += 256) {
        int row = i / 34;
        int c4 = (i % 34) * 4;
        Os[row * AQLD + c4] = 0.f;
        Os[row * AQLD + c4 + 1] = 0.f;
        Os[row * AQLD + c4 + 2] = 0.f;
        Os[row * AQLD + c4 + 3] = 0.f;
    }
    if (tid < 64) {
        Mr[tid] = -1e30f;
        Lr[tid] = 0.f;
    }
    __syncthreads();

    for (int kt = 0; kt <= qt; kt++) {
        // load K/V tiles (hi+lo)
        for (int i = tid; i < 64 * 16; i += 256) {
            int row = i >> 4;
            int c8 = (i & 15) << 3;
            int token = b * S_ + kt * 64 + row;
            size_t off = (size_t)token * (NKV_ * HD_) + hk * HD_ + c8;
            *(int4*)(Kh + row * AQLD + c8) = *(const int4*)(kh + off);
            *(int4*)(Kl + row * AQLD + c8) = *(const int4*)(kl + off);
            *(int4*)(Vh + row * AQLD + c8) = *(const int4*)(vh + off);
            *(int4*)(Vl + row * AQLD + c8) = *(const int4*)(vl + off);
        }
        __syncthreads();

        // S = Q K^T (3-term). warp tile 16x32 of the 64x64 score tile.
        {
            wmma::fragment<wmma::accumulator, 16, 16, 16, float> sacc[2];
            wmma::fill_fragment(sacc[0], 0.0f);
            wmma::fill_fragment(sacc[1], 0.0f);
            for (int ks = 0; ks < 8; ks++) {
                wmma::fragment<wmma::matrix_a, 16, 16, 16, bf16,
                               wmma::row_major> fqh, fql;
                const bf16* pq = Qh + (wm * 16) * AQLD + ks * 16;
                wmma::load_matrix_sync(fqh, pq, AQLD);
                const bf16* pq2 = Ql + (wm * 16) * AQLD + ks * 16;
                wmma::load_matrix_sync(fql, pq2, AQLD);
                for (int nj = 0; nj < 2; nj++) {
                    wmma::fragment<wmma::matrix_b, 16, 16, 16, bf16,
                                   wmma::col_major> fkh, fkl;
                    const bf16* pk =
                        Kh + (wn * 32 + nj * 16) * AQLD + ks * 16;
                    wmma::load_matrix_sync(fkh, pk, AQLD);
                    const bf16* pk2 =
                        Kl + (wn * 32 + nj * 16) * AQLD + ks * 16;
                    wmma::load_matrix_sync(fkl, pk2, AQLD);
                    wmma::mma_sync(sacc[nj], fqh, fkh, sacc[nj]);
                    wmma::mma_sync(sacc[nj], fqh, fkl, sacc[nj]);
                    wmma::mma_sync(sacc[nj], fql, fkh, sacc[nj]);
                }
            }
            for (int nj = 0; nj < 2; nj++) {
                float* ps = Ss + (wm * 16) * ASLD + wn * 32 + nj * 16;
                wmma::store_matrix_sync(ps, sacc[nj], ASLD,
                                        wmma::mem_row_major);
            }
        }
        __syncthreads();

        // online softmax per row (scale already folded into Q)
        if (tid < 64) {
            int r = tid;
            bool diag = (kt == qt);
            float mx = Mr[r];
            for (int c = 0; c < 64; c++) {
                float val = Ss[r * ASLD + c];
                if (diag && c > r) val = -1e30f;
                mx = fmaxf(mx, val);
            }
            float alpha = expf(Mr[r] - mx);
            float sum = 0.f;
            for (int c = 0; c < 64; c++) {
                float val = Ss[r * ASLD + c];
                if (diag && c > r) val = -1e30f;
                float p = expf(val - mx);
                bf16 phv = __float2bfloat16(p);
                Ph[r * ASLD + c] = phv;
                Pl[r * ASLD + c] =
                    __float2bfloat16(p - __bfloat162float(phv));
                sum += p;
            }
            Lr[r] = Lr[r] * alpha + sum;
            Mr[r] = mx;
            Ar[r] = alpha;
        }
        __syncthreads();

        // rescale O rows by alpha (128 data columns)
        for (int i = tid; i < 64 * 32; i += 256) {
            int r = i >> 5;
            int c4 = (i & 31) << 2;
            float a = Ar[r];
            float* p = Os + r * AQLD + c4;
            p[0] *= a;
            p[1] *= a;
            p[2] *= a;
            p[3] *= a;
        }
        __syncthreads();

        // O += P V (3-term). warp tile 16x64 of the 64x128 output.
        {
            wmma::fragment<wmma::accumulator, 16, 16, 16, float> oacc[4];
            for (int nj = 0; nj < 4; nj++) {
                const float* po =
                    Os + (wm * 16) * AQLD + wn * 64 + nj * 16;
                wmma::load_matrix_sync(oacc[nj], po, AQLD,
                                       wmma::mem_row_major);
            }
            for (int ks = 0; ks < 4; ks++) {
                wmma::fragment<wmma::matrix_a, 16, 16, 16, bf16,
                               wmma::row_major> fph, fpl;
                const bf16* pp = Ph + (wm * 16) * ASLD + ks * 16;
                wmma::load_matrix_sync(fph, pp, ASLD);
                const bf16* pp2 = Pl + (wm * 16) * ASLD + ks * 16;
                wmma::load_matrix_sync(fpl, pp2, ASLD);
                for (int nj = 0; nj < 4; nj++) {
                    wmma::fragment<wmma::matrix_b, 16, 16, 16, bf16,
                                   wmma::row_major> fvh, fvl;
                    const bf16* pv =
                        Vh + (ks * 16) * AQLD + wn * 64 + nj * 16;
                    wmma::load_matrix_sync(fvh, pv, AQLD);
                    const bf16* pv2 =
                        Vl + (ks * 16) * AQLD + wn * 64 + nj * 16;
                    wmma::load_matrix_sync(fvl, pv2, AQLD);
                    wmma::mma_sync(oacc[nj], fph, fvh, oacc[nj]);
                    wmma::mma_sync(oacc[nj], fph, fvl, oacc[nj]);
                    wmma::mma_sync(oacc[nj], fpl, fvh, oacc[nj]);
                }
            }
            for (int nj = 0; nj < 4; nj++) {
                float* po = Os + (wm * 16) * AQLD + wn * 64 + nj * 16;
                wmma::store_matrix_sync(po, oacc[nj], AQLD,
                                        wmma::mem_row_major);
            }
        }
        __syncthreads();
    }

    // final normalize and write bf16 pair
    for (int i = tid; i < 64 * 32; i += 256) {
        int r = i >> 5;
        int c4 = (i & 31) << 2;
        float inv = 1.0f / Lr[r];
        int token = b * S_ + qt * 64 + r;
        size_t off = (size_t)token * (NH_ * HD_) + h * HD_ + c4;
        for (int j = 0; j < 4; j++) {
            float val = Os[r * AQLD + c4 + j] * inv;
            bf16 hv = __float2bfloat16(val);
            oh[off + j] = hv;
            ol[off + j] = __float2bfloat16(val - __bfloat162float(hv));
        }
    }
}

// ---------------- SiLU(g)*u -> bf16 pair ----------------
__global__ void silumul_kernel(const float* __restrict__ g,
                               const float* __restrict__ u,
                               bf16* __restrict__ oh,
                               bf16* __restrict__ ol,
                               const int* __restrict__ counts) {
    int z = blockIdx.y;
    int M = counts ? counts[z] : T_;
    int idx = (blockIdx.x * 256 + threadIdx.x) * 4;
    if (idx >= T_ * I_) return;
    if ((idx / I_) >= M) return;
    size_t base = (size_t)z * T_ * I_ + idx;
    float4 gv = *(const float4*)(g + base);
    float4 uv = *(const float4*)(u + base);
    float a0 = gv.x / (1.f + expf(-gv.x)) * uv.x;
    float a1 = gv.y / (1.f + expf(-gv.y)) * uv.y;
    float a2 = gv.z / (1.f + expf(-gv.z)) * uv.z;
    float a3 = gv.w / (1.f + expf(-gv.w)) * uv.w;
    bf16 h0 = __float2bfloat16(a0);
    bf16 h1 = __float2bfloat16(a1);
    bf16 h2 = __float2bfloat16(a2);
    bf16 h3 = __float2bfloat16(a3);
    __nv_bfloat162* H2 = (__nv_bfloat162*)(oh + base);
    __nv_bfloat162* L2 = (__nv_bfloat162*)(ol + base);
    H2[0] = __halves2bfloat162(h0, h1);
    H2[1] = __halves2bfloat162(h2, h3);
    bf16 l0 = __float2bfloat16(a0 - __bfloat162float(h0));
    bf16 l1 = __float2bfloat16(a1 - __bfloat162float(h1));
    bf16 l2 = __float2bfloat16(a2 - __bfloat162float(h2));
    bf16 l3 = __float2bfloat16(a3 - __bfloat162float(h3));
    L2[0] = __halves2bfloat162(l0, l1);
    L2[1] = __halves2bfloat162(l2, l3);
}

// ---------------- router ----------------
__global__ void zero_cnt_kernel(int* cnt) {
    if (threadIdx.x < E_) cnt[threadIdx.x] = 0;
}

__global__ void router_kernel(const float* __restrict__ xn2,
                              const float* __restrict__ rw,
                              int* __restrict__ cnt, int* __restrict__ list,
                              int* __restrict__ slot_e,
                              int* __restrict__ slot_p,
                              float* __restrict__ slot_w) {
    int t = blockIdx.x * 8 + (threadIdx.x >> 5);
    int lane = threadIdx.x & 31;
    if (t >= T_) return;
    const float* x = xn2 + (size_t)t * H_;
    float s[E_];
    for (int e = 0; e < E_; e++) s[e] = 0.f;
    for (int i = lane; i < H_; i += 32) {
        float xv = x[i];
        for (int e = 0; e < E_; e++) s[e] += xv * rw[i * E_ + e];
    }
    for (int off = 16; off > 0; off >>= 1)
        for (int e = 0; e < E_; e++)
            s[e] += __shfl_down_sync(0xffffffffu, s[e], off);
    if (lane == 0) {
        float se[E_];
        for (int e = 0; e < E_; e++) se[e] = fmaxf(s[e], 0.f);
        int i1 = 0;
        float v1 = se[0];
        for (int e = 1; e < E_; e++) {
            if (se[e] > v1) { v1 = se[e]; i1 = e; }
        }
        int i2 = -1;
        float v2 = -1.f;
        for (int e = 0; e < E_; e++) {
            if (e != i1 && se[e] > v2) { v2 = se[e]; i2 = e; }
        }
        float denom = v1 + v2 + 1e-6f;
        float w1 = v1 / denom;
        float w2 = v2 / denom;
        int p1 = atomicAdd(&cnt[i1], 1);
        list[i1 * T_ + p1] = t;
        int p2 = atomicAdd(&cnt[i2], 1);
        list[i2 * T_ + p2] = t;
        slot_e[t * 2] = i1;
        slot_p[t * 2] = p1;
        slot_w[t * 2] = w1;
        slot_e[t * 2 + 1] = i2;
        slot_p[t * 2 + 1] = p2;
        slot_w[t * 2 + 1] = w2;
    }
}

// ---------------- final combine ----------------
__global__ void combine_kernel(const float* __restrict__ hidden,
                               const float* __restrict__ shout,
                               const float* __restrict__ eout,
                               const int* __restrict__ slot_e,
                               const int* __restrict__ slot_p,
                               const float* __restrict__ slot_w,
                               float* __restrict__ out) {
    int t = blockIdx.x;
    int e0 = slot_e[t * 2];
    int e1 = slot_e[t * 2 + 1];
    int p0 = slot_p[t * 2];
    int p1 = slot_p[t * 2 + 1];
    float w0 = slot_w[t * 2];
    float w1 = slot_w[t * 2 + 1];
    const float* r0 = eout + ((size_t)e0 * T_ + p0) * H_;
    const float* r1 = eout + ((size_t)e1 * T_ + p1) * H_;
    const float* hd = hidden + (size_t)t * H_;
    const float* sh = shout + (size_t)t * H_;
    float* op = out + (size_t)t * H_;
    for (int i = threadIdx.x; i < H_; i += 256)
        op[i] = hd[i] + sh[i] + w0 * r0[i] + w1 * r1[i];
}

// ---------------- launch ----------------
static void conv(const float* src, bf16* h, bf16* l, int n) {
    conv_kernel<<<(n / 4 + 255) / 256, 256>>>(src, h, l, n);
}

extern "C" void kernel_launch(void* const* d_in, const int* in_sizes,
                              int n_in, void* d_out, int out_size) {
    const float* hs  = (const float*)d_in[0];
    const float* ln1 = (const float*)d_in[1];
    const float* ln2 = (const float*)d_in[2];
    const float* wq  = (const float*)d_in[3];
    const float* wk  = (const float*)d_in[4];
    const float* wv  = (const float*)d_in[5];
    const float* wo  = (const float*)d_in[6];
    const float* rw  = (const float*)d_in[7];
    const float* eg  = (const float*)d_in[8];
    const float* eu  = (const float*)d_in[9];
    const float* ed  = (const float*)d_in[10];
    const float* sg  = (const float*)d_in[11];
    const float* su  = (const float*)d_in[12];
    const float* sd  = (const float*)d_in[13];
    float* out = (float*)d_out;

    float *q, *k, *v, *hidden, *xn2f, *shg, *shu, *shout, *mg, *mu, *eout;
    float *slot_w;
    int *cnt, *list, *slot_e, *slot_p;
    bf16 *xn1h, *xn1l, *attnh, *attnl, *xn2h, *xn2l;
    bf16 *shah, *shal, *mah, *mal;
    bf16 *qph, *qpl, *kph, *kpl, *vph, *vpl;
    bf16 *wqh, *wql, *wkh, *wkl, *wvh, *wvl, *woh, *wol;
    bf16 *sgh, *sgl, *suh, *sul, *sdh, *sdl;
    bf16 *egh, *egl, *euh, *eul, *edh, *edl;

    cudaGetSymbolAddress((void**)&q, g_q);
    cudaGetSymbolAddress((void**)&k, g_k);
    cudaGetSymbolAddress((void**)&v, g_v);
    cudaGetSymbolAddress((void**)&hidden, g_hidden);
    cudaGetSymbolAddress((void**)&xn2f, g_xn2f);
    cudaGetSymbolAddress((void**)&shg, g_shg);
    cudaGetSymbolAddress((void**)&shu, g_shu);
    cudaGetSymbolAddress((void**)&shout, g_shout);
    cudaGetSymbolAddress((void**)&mg, g_mg);
    cudaGetSymbolAddress((void**)&mu, g_mu);
    cudaGetSymbolAddress((void**)&eout, g_eout);
    cudaGetSymbolAddress((void**)&cnt, g_cnt);
    cudaGetSymbolAddress((void**)&list, g_list);
    cudaGetSymbolAddress((void**)&slot_e, g_slot_e);
    cudaGetSymbolAddress((void**)&slot_p, g_slot_p);
    cudaGetSymbolAddress((void**)&slot_w, g_slot_w);
    cudaGetSymbolAddress((void**)&xn1h, g_xn1h);
    cudaGetSymbolAddress((void**)&xn1l, g_xn1l);
    cudaGetSymbolAddress((void**)&attnh, g_attnh);
    cudaGetSymbolAddress((void**)&attnl, g_attnl);
    cudaGetSymbolAddress((void**)&xn2h, g_xn2h);
    cudaGetSymbolAddress((void**)&xn2l, g_xn2l);
    cudaGetSymbolAddress((void**)&shah, g_shah);
    cudaGetSymbolAddress((void**)&shal, g_shal);
    cudaGetSymbolAddress((void**)&mah, g_mah);
    cudaGetSymbolAddress((void**)&mal, g_mal);
    cudaGetSymbolAddress((void**)&qph, g_qph);
    cudaGetSymbolAddress((void**)&qpl, g_qpl);
    cudaGetSymbolAddress((void**)&kph, g_kph);
    cudaGetSymbolAddress((void**)&kpl, g_kpl);
    cudaGetSymbolAddress((void**)&vph, g_vph);
    cudaGetSymbolAddress((void**)&vpl, g_vpl);
    cudaGetSymbolAddress((void**)&wqh, g_wqh);
    cudaGetSymbolAddress((void**)&wql, g_wql);
    cudaGetSymbolAddress((void**)&wkh, g_wkh);
    cudaGetSymbolAddress((void**)&wkl, g_wkl);
    cudaGetSymbolAddress((void**)&wvh, g_wvh);
    cudaGetSymbolAddress((void**)&wvl, g_wvl);
    cudaGetSymbolAddress((void**)&woh, g_woh);
    cudaGetSymbolAddress((void**)&wol, g_wol);
    cudaGetSymbolAddress((void**)&sgh, g_sgh);
    cudaGetSymbolAddress((void**)&sgl, g_sgl);
    cudaGetSymbolAddress((void**)&suh, g_suh);
    cudaGetSymbolAddress((void**)&sul, g_sul);
    cudaGetSymbolAddress((void**)&sdh, g_sdh);
    cudaGetSymbolAddress((void**)&sdl, g_sdl);
    cudaGetSymbolAddress((void**)&egh, g_egh);
    cudaGetSymbolAddress((void**)&egl, g_egl);
    cudaGetSymbolAddress((void**)&euh, g_euh);
    cudaGetSymbolAddress((void**)&eul, g_eul);
    cudaGetSymbolAddress((void**)&edh, g_edh);
    cudaGetSymbolAddress((void**)&edl, g_edl);

    cudaFuncSetAttribute(attn_wmma_kernel,
                         cudaFuncAttributeMaxDynamicSharedMemorySize,
                         ATTN_SMEM2);

    // 0) split weights into bf16 hi/lo
    conv(wq, wqh, wql, H_ * NH_ * HD_);
    conv(wk, wkh, wkl, H_ * NKV_ * HD_);
    conv(wv, wvh, wvl, H_ * NKV_ * HD_);
    conv(wo, woh, wol, NH_ * HD_ * H_);
    conv(sg, sgh, sgl, H_ * I_);
    conv(su, suh, sul, H_ * I_);
    conv(sd, sdh, sdl, I_ * H_);
    conv(eg, egh, egl, E_ * H_ * I_);
    conv(eu, euh, eul, E_ * H_ * I_);
    conv(ed, edh, edl, E_ * I_ * H_);

    // 1) ln1
    rmsnorm_pair_kernel<<<T_, 256>>>(hs, ln1, xn1h, xn1l, (float*)0);
    // 2) qkv projections (tensor cores)
    wmma_gemm_kernel<<<dim3(16, 32, 1), 256>>>(
        xn1h, xn1l, 0, wqh, wql, 0, q, 0, (const float*)0,
        T_, NH_ * HD_, H_, (const int*)0, (const int*)0);
    wmma_gemm_kernel<<<dim3(4, 32, 1), 256>>>(
        xn1h, xn1l, 0, wkh, wkl, 0, k, 0, (const float*)0,
        T_, NKV_ * HD_, H_, (const int*)0, (const int*)0);
    wmma_gemm_kernel<<<dim3(4, 32, 1), 256>>>(
        xn1h, xn1l, 0, wvh, wvl, 0, v, 0, (const float*)0,
        T_, NKV_ * HD_, H_, (const int*)0, (const int*)0);
    // 3) RoPE -> bf16 pairs (scale folded into q); v split too
    rope_pair_kernel<<<(T_ * NH_ * 64 + 255) / 256, 256>>>(
        q, qph, qpl, NH_, 0.08838834764831845f);
    rope_pair_kernel<<<(T_ * NKV_ * 64 + 255) / 256, 256>>>(
        k, kph, kpl, NKV_, 1.0f);
    conv(v, vph, vpl, T_ * NKV_ * HD_);
    // 4) attention (wmma flash)
    attn_wmma_kernel<<<dim3(S_ / 64, NH_, B_), 256, ATTN_SMEM2>>>(
        qph, qpl, kph, kpl, vph, vpl, attnh, attnl);
    // 5) o-proj + residual
    wmma_gemm_kernel<<<dim3(16, 32, 1), 256>>>(
        attnh, attnl, 0, woh, wol, 0, hidden, 0, hs,
        T_, H_, NH_ * HD_, (const int*)0, (const int*)0);
    // 6) ln2
    rmsnorm_pair_kernel<<<T_, 256>>>(hidden, ln2, xn2h, xn2l, xn2f);
    // 7) shared expert
    wmma_gemm_kernel<<<dim3(8, 32, 1), 256>>>(
        xn2h, xn2l, 0, sgh, sgl, 0, shg, 0, (const float*)0,
        T_, I_, H_, (const int*)0, (const int*)0);
    wmma_gemm_kernel<<<dim3(8, 32, 1), 256>>>(
        xn2h, xn2l, 0, suh, sul, 0, shu, 0, (const float*)0,
        T_, I_, H_, (const int*)0, (const int*)0);
    silumul_kernel<<<dim3(T_ * I_ / 1024, 1), 256>>>(
        shg, shu, shah, shal, (const int*)0);
    wmma_gemm_kernel<<<dim3(16, 32, 1), 256>>>(
        shah, shal, 0, sdh, sdl, 0, shout, 0, (const float*)0,
        T_, H_, I_, (const int*)0, (const int*)0);
    // 8) router + scatter
    zero_cnt_kernel<<<1, 32>>>(cnt);
    router_kernel<<<T_ / 8, 256>>>(xn2f, rw, cnt, list, slot_e, slot_p,
                                   slot_w);
    // 9) routed experts
    wmma_gemm_kernel<<<dim3(8, 32, E_), 256>>>(
        xn2h, xn2l, 0, egh, egl, (size_t)H_ * I_, mg, (size_t)T_ * I_,
        (const float*)0, T_, I_, H_, cnt, list);
    wmma_gemm_kernel<<<dim3(8, 32, E_), 256>>>(
        xn2h, xn2l, 0, euh, eul, (size_t)H_ * I_, mu, (size_t)T_ * I_,
        (const float*)0, T_, I_, H_, cnt, list);
    silumul_kernel<<<dim3(T_ * I_ / 1024, E_), 256>>>(mg, mu, mah, mal, cnt);
    wmma_gemm_kernel<<<dim3(16, 32, E_), 256>>>(
        mah, mal, (size_t)T_ * I_, edh, edl, (size_t)I_ * H_, eout,
        (size_t)T_ * H_, (const float*)0, T_, H_, I_, cnt, (const int*)0);
    // 10) combine
    combine_kernel<<<T_, 256>>>(hidden, shout, eout, slot_e, slot_p,
                                slot_w, out);
}

// round 10
// speedup vs baseline: 1.9166x; 1.3387x over previous
#include <cuda_runtime.h>
#include <cuda_bf16.h>
#include <cuda_pipeline.h>
#include <mma.h>
#include <math.h>

using namespace nvcuda;
typedef __nv_bfloat16 bf16;

// ---------------- problem constants ----------------
constexpr int B_  = 2;
constexpr int S_  = 2048;
constexpr int H_  = 2048;
constexpr int NH_ = 16;
constexpr int NKV_= 4;
constexpr int HD_ = 128;
constexpr int T_  = B_ * S_;
constexpr int E_  = 8;
constexpr int I_  = 1024;
constexpr float EPS_ = 1e-5f;
constexpr float THETA_ = 500000.0f;

// ---------------- scratch (device globals) ----------------
__device__ float g_q[T_ * NH_ * HD_];
__device__ float g_k[T_ * NKV_ * HD_];
__device__ float g_v[T_ * NKV_ * HD_];
__device__ float g_hidden[T_ * H_];
__device__ float g_xn2f[T_ * H_];
__device__ float g_shg[T_ * I_];
__device__ float g_shu[T_ * I_];
__device__ float g_shout[T_ * H_];
__device__ float g_mg[(size_t)E_ * T_ * I_];
__device__ float g_mu[(size_t)E_ * T_ * I_];
__device__ float g_eout[(size_t)E_ * T_ * H_];

__device__ bf16 g_xn1h[T_ * H_];
__device__ bf16 g_xn1l[T_ * H_];
__device__ bf16 g_attnh[T_ * NH_ * HD_];
__device__ bf16 g_attnl[T_ * NH_ * HD_];
__device__ bf16 g_xn2h[T_ * H_];
__device__ bf16 g_xn2l[T_ * H_];
__device__ bf16 g_shah[T_ * I_];
__device__ bf16 g_shal[T_ * I_];
__device__ bf16 g_mah[(size_t)E_ * T_ * I_];
__device__ bf16 g_mal[(size_t)E_ * T_ * I_];

// attention bf16 pair operands
__device__ bf16 g_qph[T_ * NH_ * HD_];
__device__ bf16 g_qpl[T_ * NH_ * HD_];
__device__ bf16 g_kph[T_ * NKV_ * HD_];
__device__ bf16 g_kpl[T_ * NKV_ * HD_];
__device__ bf16 g_vph[T_ * NKV_ * HD_];
__device__ bf16 g_vpl[T_ * NKV_ * HD_];

__device__ bf16 g_wqh[H_ * NH_ * HD_];
__device__ bf16 g_wql[H_ * NH_ * HD_];
__device__ bf16 g_wkh[H_ * NKV_ * HD_];
__device__ bf16 g_wkl[H_ * NKV_ * HD_];
__device__ bf16 g_wvh[H_ * NKV_ * HD_];
__device__ bf16 g_wvl[H_ * NKV_ * HD_];
__device__ bf16 g_woh[NH_ * HD_ * H_];
__device__ bf16 g_wol[NH_ * HD_ * H_];
__device__ bf16 g_sgh[H_ * I_];
__device__ bf16 g_sgl[H_ * I_];
__device__ bf16 g_suh[H_ * I_];
__device__ bf16 g_sul[H_ * I_];
__device__ bf16 g_sdh[I_ * H_];
__device__ bf16 g_sdl[I_ * H_];
__device__ bf16 g_egh[(size_t)E_ * H_ * I_];
__device__ bf16 g_egl[(size_t)E_ * H_ * I_];
__device__ bf16 g_euh[(size_t)E_ * H_ * I_];
__device__ bf16 g_eul[(size_t)E_ * H_ * I_];
__device__ bf16 g_edh[(size_t)E_ * I_ * H_];
__device__ bf16 g_edl[(size_t)E_ * I_ * H_];

__device__ int   g_cnt[E_];
__device__ int   g_list[E_ * T_];
__device__ int   g_slot_e[T_ * 2];
__device__ int   g_slot_p[T_ * 2];
__device__ float g_slot_w[T_ * 2];

// ---------------- fp32 -> bf16 hi/lo split (grid-stride) ----------------
__global__ void conv_kernel(const float* __restrict__ src,
                            bf16* __restrict__ hi,
                            bf16* __restrict__ lo, int n) {
    int stride = gridDim.x * blockDim.x;
    for (int t = blockIdx.x * blockDim.x + threadIdx.x; t * 4 < n;
         t += stride) {
        int i = t * 4;
        float4 v = *(const float4*)(src + i);
        bf16 h0 = __float2bfloat16(v.x);
        bf16 h1 = __float2bfloat16(v.y);
        bf16 h2 = __float2bfloat16(v.z);
        bf16 h3 = __float2bfloat16(v.w);
        bf16 l0 = __float2bfloat16(v.x - __bfloat162float(h0));
        bf16 l1 = __float2bfloat16(v.y - __bfloat162float(h1));
        bf16 l2 = __float2bfloat16(v.z - __bfloat162float(h2));
        bf16 l3 = __float2bfloat16(v.w - __bfloat162float(h3));
        __nv_bfloat162* H2 = (__nv_bfloat162*)(hi + i);
        __nv_bfloat162* L2 = (__nv_bfloat162*)(lo + i);
        H2[0] = __halves2bfloat162(h0, h1);
        H2[1] = __halves2bfloat162(h2, h3);
        L2[0] = __halves2bfloat162(l0, l1);
        L2[1] = __halves2bfloat162(l2, l3);
    }
}

// ---------------- RMSNorm -> bf16 pair (+ optional fp32 copy) ----------------
__global__ void rmsnorm_pair_kernel(const float* __restrict__ in,
                                    const float* __restrict__ w,
                                    bf16* __restrict__ oh,
                                    bf16* __restrict__ ol,
                                    float* __restrict__ of) {
    int t = blockIdx.x;
    const float* x = in + (size_t)t * H_;
    float ss = 0.f;
    for (int i = threadIdx.x; i < H_; i += 256) {
        float vv = x[i];
        ss += vv * vv;
    }
    __shared__ float red[256];
    red[threadIdx.x] = ss;
    __syncthreads();
    for (int s2 = 128; s2 > 0; s2 >>= 1) {
        if (threadIdx.x < s2) red[threadIdx.x] += red[threadIdx.x + s2];
        __syncthreads();
    }
    float rs = rsqrtf(red[0] / (float)H_ + EPS_);
    size_t base = (size_t)t * H_;
    for (int i = threadIdx.x; i < H_; i += 256) {
        float y = w[i] * x[i] * rs;
        bf16 h = __float2bfloat16(y);
        oh[base + i] = h;
        ol[base + i] = __float2bfloat16(y - __bfloat162float(h));
        if (of) of[base + i] = y;
    }
}

// ============================================================================
// padding banner
// ----------------------------------------------------------------------------
// Inline PTX asm string literals get mangled by the submission transport
// (parse-error cascades near line 250 in earlier rounds), so this file uses
// only C++ APIs for tensor-core and async-copy work: nvcuda::wmma fragments
// and __pipeline_memcpy_async / __pipeline_commit / __pipeline_wait_prior
// from cuda_pipeline.h (these compile to LDGSTS with no asm strings here).
// This banner also keeps the byte region around line ~250 inside comments.
//
// Round 10 changes (scheduling only, numerics identical):
//  (a) The GEMM below is now double-buffered: a 2-stage ping-pong in dynamic
//      shared memory, with the k+1 tile fetched via the pipeline API while
//      tile k is consumed by wmma. Out-of-range A rows are zero-filled with
//      plain stores (the pipeline API has no zero-fill).
//  (b) The attention online-softmax now uses all 256 threads (4 threads per
//      row, 16 columns each, shfl-xor reductions for row max and sum)
//      instead of 64 serial row-threads.
//  (c) conv_kernel is grid-stride with a capped grid so each thread streams
//      several independent 16-byte chunks (MLP >= 4).
//
// Numerics (bf16x3 split, unchanged): x ~= hi + lo, hi = bf16(x),
// lo = bf16(x - hi); A x B ~= Ah*Bh + Ah*Bl + Al*Bh with fp32 accumulators.
// Layer relative error ~1.2e-5, threshold 1e-3.
//
// Attention: one CTA per 64 query rows per (head, batch); K/V stream through
// smem; S = Q K^T and O += P V both 3-term; exact fp32 online softmax; O in
// smem fp32 with per-step alpha rescale; 1/sqrt(HD) folded into Q at RoPE.
// ============================================================================

constexpr int GLDA = 40;    // A smem stride (32 + 8 pad)
constexpr int GLDB = 136;   // B smem stride (128 + 8 pad)
constexpr int ATILE = 128 * GLDA;
constexpr int BTILE = 32 * GLDB;
constexpr int STAGE_ELEMS = 2 * ATILE + 2 * BTILE;   // 18944 bf16
constexpr int GEMM_SMEM = 2 * STAGE_ELEMS * 2;       // 75776 bytes

__global__ void __launch_bounds__(256)
wmma_gemm_kernel(const bf16* __restrict__ Ah, const bf16* __restrict__ Al,
                 size_t sA,
                 const bf16* __restrict__ Bh, const bf16* __restrict__ Bl,
                 size_t sB,
                 float* __restrict__ C, size_t sC,
                 const float* __restrict__ addend,
                 int M, int N, int K,
                 const int* __restrict__ counts,
                 const int* __restrict__ lists) {
    extern __shared__ __align__(16) bf16 smg[];

    int z = blockIdx.z;
    int Mz = M;
    if (counts) {
        int c = counts[z];
        if (c < Mz) Mz = c;
    }
    int m0 = blockIdx.y * 128;
    if (m0 >= Mz) return;
    int n0 = blockIdx.x * 128;
    Ah += (size_t)z * sA;
    Al += (size_t)z * sA;
    Bh += (size_t)z * sB;
    Bl += (size_t)z * sB;
    C += (size_t)z * sC;
    if (addend) addend += (size_t)z * sC;
    const int* lst = lists ? (lists + (size_t)z * T_) : (const int*)0;

    int tid = threadIdx.x;
    int w = tid >> 5;
    int wm = w >> 1;
    int wn = w & 1;

    // per-thread load coordinates (fixed across stages)
    int aRow = tid >> 1;               // 0..127 (2 threads per row)
    int aCol = (tid & 1) << 4;         // 0 or 16 (two 8-elem chunks each)
    int bRow = tid >> 3;               // 0..31
    int bCol = (tid & 7) << 4;         // 0..112 step 16

    wmma::fragment<wmma::accumulator, 16, 16, 16, float> acc[2][4];
    for (int mi = 0; mi < 2; mi++)
        for (int nj = 0; nj < 4; nj++)
            wmma::fill_fragment(acc[mi][nj], 0.0f);

    int nk = K / 32;

    // stage loader: issues async copies for tile starting at k0 into stage st
    auto load_stage = [&](int k0, int st) {
        bf16* sAh = smg + st * STAGE_ELEMS;
        bf16* sAl = sAh + ATILE;
        bf16* sBh = sAl + ATILE;
        bf16* sBl = sBh + BTILE;
        int grow = m0 + aRow;
        bf16* dh = sAh + aRow * GLDA + aCol;
        bf16* dl = sAl + aRow * GLDA + aCol;
        if (grow < Mz) {
            int arow = lst ? lst[grow] : grow;
            size_t off = (size_t)arow * K + k0 + aCol;
            __pipeline_memcpy_async(dh, Ah + off, 16);
            __pipeline_memcpy_async(dh + 8, Ah + off + 8, 16);
            __pipeline_memcpy_async(dl, Al + off, 16);
            __pipeline_memcpy_async(dl + 8, Al + off + 8, 16);
        } else {
            int4 zz = make_int4(0, 0, 0, 0);
            *(int4*)dh = zz;
            *(int4*)(dh + 8) = zz;
            *(int4*)dl = zz;
            *(int4*)(dl + 8) = zz;
        }
        size_t boff = (size_t)(k0 + bRow) * N + n0 + bCol;
        bf16* ebh = sBh + bRow * GLDB + bCol;
        bf16* ebl = sBl + bRow * GLDB + bCol;
        __pipeline_memcpy_async(ebh, Bh + boff, 16);
        __pipeline_memcpy_async(ebh + 8, Bh + boff + 8, 16);
        __pipeline_memcpy_async(ebl, Bl + boff, 16);
        __pipeline_memcpy_async(ebl + 8, Bl + boff + 8, 16);
    };

    load_stage(0, 0);
    __pipeline_commit();

    for (int ki = 0; ki < nk; ki++) {
        if (ki + 1 < nk) {
            load_stage((ki + 1) * 32, (ki + 1) & 1);
            __pipeline_commit();
            __pipeline_wait_prior(1);
        } else {
            __pipeline_wait_prior(0);
        }
        __syncthreads();

        int st = ki & 1;
        bf16* sAh = smg + st * STAGE_ELEMS;
        bf16* sAl = sAh + ATILE;
        bf16* sBh = sAl + ATILE;
        bf16* sBl = sBh + BTILE;

        for (int kb = 0; kb < 32; kb += 16) {
            wmma::fragment<wmma::matrix_a, 16, 16, 16, bf16,
                           wmma::row_major> fah[2], fal[2];
            for (int mi = 0; mi < 2; mi++) {
                const bf16* pa = sAh + (wm * 32 + mi * 16) * GLDA + kb;
                wmma::load_matrix_sync(fah[mi], pa, GLDA);
                const bf16* pl = sAl + (wm * 32 + mi * 16) * GLDA + kb;
                wmma::load_matrix_sync(fal[mi], pl, GLDA);
            }
            wmma::fragment<wmma::matrix_b, 16, 16, 16, bf16,
                           wmma::row_major> fbh[4], fbl[4];
            for (int nj = 0; nj < 4; nj++) {
                const bf16* pb = sBh + kb * GLDB + wn * 64 + nj * 16;
                wmma::load_matrix_sync(fbh[nj], pb, GLDB);
                const bf16* pl = sBl + kb * GLDB + wn * 64 + nj * 16;
                wmma::load_matrix_sync(fbl[nj], pl, GLDB);
            }
            for (int mi = 0; mi < 2; mi++) {
                for (int nj = 0; nj < 4; nj++) {
                    wmma::mma_sync(acc[mi][nj], fah[mi], fbh[nj],
                                   acc[mi][nj]);
                    wmma::mma_sync(acc[mi][nj], fah[mi], fbl[nj],
                                   acc[mi][nj]);
                    wmma::mma_sync(acc[mi][nj], fal[mi], fbh[nj],
                                   acc[mi][nj]);
                }
            }
        }
        __syncthreads();
    }

    for (int mi = 0; mi < 2; mi++) {
        for (int nj = 0; nj < 4; nj++) {
            int row = m0 + wm * 32 + mi * 16;
            int col = n0 + wn * 64 + nj * 16;
            float* cp = C + (size_t)row * N + col;
            if (addend) {
                wmma::fragment<wmma::accumulator, 16, 16, 16, float> fc;
                const float* ap = addend + (size_t)row * N + col;
                wmma::load_matrix_sync(fc, ap, N, wmma::mem_row_major);
                for (int e = 0; e < fc.num_elements; e++)
                    acc[mi][nj].x[e] += fc.x[e];
            }
            wmma::store_matrix_sync(cp, acc[mi][nj], N,
                                    wmma::mem_row_major);
        }
    }
}

// ---------------- RoPE -> bf16 hi/lo pair (optionally pre-scaled) ----------
__global__ void rope_pair_kernel(const float* __restrict__ src,
                                 bf16* __restrict__ oh,
                                 bf16* __restrict__ ol,
                                 int nheads, float mul) {
    int idx = blockIdx.x * blockDim.x + threadIdx.x;
    int total = T_ * nheads * (HD_ / 2);
    if (idx >= total) return;
    int d = idx & 63;
    int rest = idx >> 6;
    int h = rest % nheads;
    int t = rest / nheads;
    int pos = t % S_;
    float inv = powf(THETA_, -(float)d / 64.0f);
    float ang = (float)pos * inv;
    float c = cosf(ang);
    float sn = sinf(ang);
    size_t base = (size_t)t * nheads * HD_ + h * HD_;
    float x1 = src[base + d];
    float x2 = src[base + d + 64];
    float y1 = (x1 * c - x2 * sn) * mul;
    float y2 = (x2 * c + x1 * sn) * mul;
    bf16 h1 = __float2bfloat16(y1);
    bf16 h2 = __float2bfloat16(y2);
    oh[base + d] = h1;
    oh[base + d + 64] = h2;
    ol[base + d] = __float2bfloat16(y1 - __bfloat162float(h1));
    ol[base + d + 64] = __float2bfloat16(y2 - __bfloat162float(h2));
}

// ---------------- wmma flash attention ----------------
constexpr int AQLD = 136;   // Q/K/V/O smem stride (128 + 8)
constexpr int ASLD = 72;    // S/P smem stride (64 + 8)
constexpr int ATTN_SMEM2 =
    6 * 64 * AQLD * 2 +            // Qh Ql Kh Kl Vh Vl (bf16)
    64 * ASLD * 4 +                // S (fp32)
    2 * 64 * ASLD * 2 +            // Ph Pl (bf16)
    64 * AQLD * 4 +                // O (fp32)
    3 * 64 * 4;                    // M L A rows

__global__ void __launch_bounds__(256, 1)
attn_wmma_kernel(const bf16* __restrict__ qh, const bf16* __restrict__ ql,
                 const bf16* __restrict__ kh, const bf16* __restrict__ kl,
                 const bf16* __restrict__ vh, const bf16* __restrict__ vl,
                 bf16* __restrict__ oh, bf16* __restrict__ ol) {
    extern __shared__ char smraw[];
    bf16* Qh = (bf16*)smraw;
    bf16* Ql = Qh + 64 * AQLD;
    bf16* Kh = Ql + 64 * AQLD;
    bf16* Kl = Kh + 64 * AQLD;
    bf16* Vh = Kl + 64 * AQLD;
    bf16* Vl = Vh + 64 * AQLD;
    float* Ss = (float*)(Vl + 64 * AQLD);
    bf16* Ph = (bf16*)(Ss + 64 * ASLD);
    bf16* Pl = Ph + 64 * ASLD;
    float* Os = (float*)(Pl + 64 * ASLD);
    float* Mr = Os + 64 * AQLD;
    float* Lr = Mr + 64;
    float* Ar = Lr + 64;

    int qt = (int)(gridDim.x - 1) - (int)blockIdx.x;  // heavy CTAs first
    int h = blockIdx.y;
    int b = blockIdx.z;
    int hk = h >> 2;
    int tid = threadIdx.x;
    int w = tid >> 5;
    int wm = w >> 1;     // 0..3
    int wn = w & 1;      // 0..1

    // load Q tile (64 x 128, hi+lo), zero O, init M/L
    for (int i = tid; i < 64 * 16; i += 256) {
        int row = i >> 4;
        int c8 = (i & 15) << 3;
        int token = b * S_ + qt * 64 + row;
        size_t off = (size_t)token * (NH_ * HD_) + h * HD_ + c8;
        *(int4*)(Qh + row * AQLD + c8) = *(const int4*)(qh + off);
        *(int4*)(Ql + row * AQLD + c8) = *(const int4*)(ql + off);
    }
    // zero the full 64 x AQLD fp32 O region: 34 4-float chunks per row
    for (int i = tid; i < 64 * 34; i += 256) {
        int row = i / 34;
        int c4 = (i % 34) * 4;
        Os[row * AQLD + c4] = 0.f;
        Os[row * AQLD + c4 + 1] = 0.f;
        Os[row * AQLD + c4 + 2] = 0.f;
        Os[row * AQLD + c4 + 3] = 0.f;
    }
    if (tid < 64) {
        Mr[tid] = -1e30f;
        Lr[tid] = 0.f;
    }
    __syncthreads();

    for (int kt = 0; kt <= qt; kt++) {
        // load K/V tiles (hi+lo)
        for (int i = tid; i < 64 * 16; i += 256) {
            int row = i >> 4;
            int c8 = (i & 15) << 3;
            int token = b * S_ + kt * 64 + row;
            size_t off = (size_t)token * (NKV_ * HD_) + hk * HD_ + c8;
            *(int4*)(Kh + row * AQLD + c8) = *(const int4*)(kh + off);
            *(int4*)(Kl + row * AQLD + c8) = *(const int4*)(kl + off);
            *(int4*)(Vh + row * AQLD + c8) = *(const int4*)(vh + off);
            *(int4*)(Vl + row * AQLD + c8) = *(const int4*)(vl + off);
        }
        __syncthreads();

        // S = Q K^T (3-term). warp tile 16x32 of the 64x64 score tile.
        {
            wmma::fragment<wmma::accumulator, 16, 16, 16, float> sacc[2];
            wmma::fill_fragment(sacc[0], 0.0f);
            wmma::fill_fragment(sacc[1], 0.0f);
            for (int ks = 0; ks < 8; ks++) {
                wmma::fragment<wmma::matrix_a, 16, 16, 16, bf16,
                               wmma::row_major> fqh, fql;
                const bf16* pq = Qh + (wm * 16) * AQLD + ks * 16;
                wmma::load_matrix_sync(fqh, pq, AQLD);
                const bf16* pq2 = Ql + (wm * 16) * AQLD + ks * 16;
                wmma::load_matrix_sync(fql, pq2, AQLD);
                for (int nj = 0; nj < 2; nj++) {
                    wmma::fragment<wmma::matrix_b, 16, 16, 16, bf16,
                                   wmma::col_major> fkh, fkl;
                    const bf16* pk =
                        Kh + (wn * 32 + nj * 16) * AQLD + ks * 16;
                    wmma::load_matrix_sync(fkh, pk, AQLD);
                    const bf16* pk2 =
                        Kl + (wn * 32 + nj * 16) * AQLD + ks * 16;
                    wmma::load_matrix_sync(fkl, pk2, AQLD);
                    wmma::mma_sync(sacc[nj], fqh, fkh, sacc[nj]);
                    wmma::mma_sync(sacc[nj], fqh, fkl, sacc[nj]);
                    wmma::mma_sync(sacc[nj], fql, fkh, sacc[nj]);
                }
            }
            for (int nj = 0; nj < 2; nj++) {
                float* ps = Ss + (wm * 16) * ASLD + wn * 32 + nj * 16;
                wmma::store_matrix_sync(ps, sacc[nj], ASLD,
                                        wmma::mem_row_major);
            }
        }
        __syncthreads();

        // online softmax: 4 threads per row, 16 columns each
        {
            int r = tid >> 2;
            int sub = tid & 3;
            int c0 = sub * 16;
            bool diag = (kt == qt);
            float mOld = Mr[r];
            float mx = mOld;
            for (int c = c0; c < c0 + 16; c++) {
                float val = Ss[r * ASLD + c];
                if (diag && c > r) val = -1e30f;
                mx = fmaxf(mx, val);
            }
            mx = fmaxf(mx, __shfl_xor_sync(0xffffffffu, mx, 1));
            mx = fmaxf(mx, __shfl_xor_sync(0xffffffffu, mx, 2));
            float sum = 0.f;
            for (int c = c0; c < c0 + 16; c++) {
                float val = Ss[r * ASLD + c];
                if (diag && c > r) val = -1e30f;
                float p = expf(val - mx);
                bf16 phv = __float2bfloat16(p);
                Ph[r * ASLD + c] = phv;
                Pl[r * ASLD + c] =
                    __float2bfloat16(p - __bfloat162float(phv));
                sum += p;
            }
            sum += __shfl_xor_sync(0xffffffffu, sum, 1);
            sum += __shfl_xor_sync(0xffffffffu, sum, 2);
            if (sub == 0) {
                float alpha = expf(mOld - mx);
                Lr[r] = Lr[r] * alpha + sum;
                Mr[r] = mx;
                Ar[r] = alpha;
            }
        }
        __syncthreads();

        // rescale O rows by alpha (128 data columns)
        for (int i = tid; i < 64 * 32; i += 256) {
            int r = i >> 5;
            int c4 = (i & 31) << 2;
            float a = Ar[r];
            float* p = Os + r * AQLD + c4;
            p[0] *= a;
            p[1] *= a;
            p[2] *= a;
            p[3] *= a;
        }
        __syncthreads();

        // O += P V (3-term). warp tile 16x64 of the 64x128 output.
        {
            wmma::fragment<wmma::accumulator, 16, 16, 16, float> oacc[4];
            for (int nj = 0; nj < 4; nj++) {
                const float* po =
                    Os + (wm * 16) * AQLD + wn * 64 + nj * 16;
                wmma::load_matrix_sync(oacc[nj], po, AQLD,
                                       wmma::mem_row_major);
            }
            for (int ks = 0; ks < 4; ks++) {
                wmma::fragment<wmma::matrix_a, 16, 16, 16, bf16,
                               wmma::row_major> fph, fpl;
                const bf16* pp = Ph + (wm * 16) * ASLD + ks * 16;
                wmma::load_matrix_sync(fph, pp, ASLD);
                const bf16* pp2 = Pl + (wm * 16) * ASLD + ks * 16;
                wmma::load_matrix_sync(fpl, pp2, ASLD);
                for (int nj = 0; nj < 4; nj++) {
                    wmma::fragment<wmma::matrix_b, 16, 16, 16, bf16,
                                   wmma::row_major> fvh, fvl;
                    const bf16* pv =
                        Vh + (ks * 16) * AQLD + wn * 64 + nj * 16;
                    wmma::load_matrix_sync(fvh, pv, AQLD);
                    const bf16* pv2 =
                        Vl + (ks * 16) * AQLD + wn * 64 + nj * 16;
                    wmma::load_matrix_sync(fvl, pv2, AQLD);
                    wmma::mma_sync(oacc[nj], fph, fvh, oacc[nj]);
                    wmma::mma_sync(oacc[nj], fph, fvl, oacc[nj]);
                    wmma::mma_sync(oacc[nj], fpl, fvh, oacc[nj]);
                }
            }
            for (int nj = 0; nj < 4; nj++) {
                float* po = Os + (wm * 16) * AQLD + wn * 64 + nj * 16;
                wmma::store_matrix_sync(po, oacc[nj], AQLD,
                                        wmma::mem_row_major);
            }
        }
        __syncthreads();
    }

    // final normalize and write bf16 pair
    for (int i = tid; i < 64 * 32; i += 256) {
        int r = i >> 5;
        int c4 = (i & 31) << 2;
        float inv = 1.0f / Lr[r];
        int token = b * S_ + qt * 64 + r;
        size_t off = (size_t)token * (NH_ * HD_) + h * HD_ + c4;
        for (int j = 0; j < 4; j++) {
            float val = Os[r * AQLD + c4 + j] * inv;
            bf16 hv = __float2bfloat16(val);
            oh[off + j] = hv;
            ol[off + j] = __float2bfloat16(val - __bfloat162float(hv));
        }
    }
}

// ---------------- SiLU(g)*u -> bf16 pair ----------------
__global__ void silumul_kernel(const float* __restrict__ g,
                               const float* __restrict__ u,
                               bf16* __restrict__ oh,
                               bf16* __restrict__ ol,
                               const int* __restrict__ counts) {
    int z = blockIdx.y;
    int M = counts ? counts[z] : T_;
    int idx = (blockIdx.x * 256 + threadIdx.x) * 4;
    if (idx >= T_ * I_) return;
    if ((idx / I_) >= M) return;
    size_t base = (size_t)z * T_ * I_ + idx;
    float4 gv = *(const float4*)(g + base);
    float4 uv = *(const float4*)(u + base);
    float a0 = gv.x / (1.f + expf(-gv.x)) * uv.x;
    float a1 = gv.y / (1.f + expf(-gv.y)) * uv.y;
    float a2 = gv.z / (1.f + expf(-gv.z)) * uv.z;
    float a3 = gv.w / (1.f + expf(-gv.w)) * uv.w;
    bf16 h0 = __float2bfloat16(a0);
    bf16 h1 = __float2bfloat16(a1);
    bf16 h2 = __float2bfloat16(a2);
    bf16 h3 = __float2bfloat16(a3);
    __nv_bfloat162* H2 = (__nv_bfloat162*)(oh + base);
    __nv_bfloat162* L2 = (__nv_bfloat162*)(ol + base);
    H2[0] = __halves2bfloat162(h0, h1);
    H2[1] = __halves2bfloat162(h2, h3);
    bf16 l0 = __float2bfloat16(a0 - __bfloat162float(h0));
    bf16 l1 = __float2bfloat16(a1 - __bfloat162float(h1));
    bf16 l2 = __float2bfloat16(a2 - __bfloat162float(h2));
    bf16 l3 = __float2bfloat16(a3 - __bfloat162float(h3));
    L2[0] = __halves2bfloat162(l0, l1);
    L2[1] = __halves2bfloat162(l2, l3);
}

// ---------------- router ----------------
__global__ void zero_cnt_kernel(int* cnt) {
    if (threadIdx.x < E_) cnt[threadIdx.x] = 0;
}

__global__ void router_kernel(const float* __restrict__ xn2,
                              const float* __restrict__ rw,
                              int* __restrict__ cnt, int* __restrict__ list,
                              int* __restrict__ slot_e,
                              int* __restrict__ slot_p,
                              float* __restrict__ slot_w) {
    int t = blockIdx.x * 8 + (threadIdx.x >> 5);
    int lane = threadIdx.x & 31;
    if (t >= T_) return;
    const float* x = xn2 + (size_t)t * H_;
    float s[E_];
    for (int e = 0; e < E_; e++) s[e] = 0.f;
    for (int i = lane; i < H_; i += 32) {
        float xv = x[i];
        for (int e = 0; e < E_; e++) s[e] += xv * rw[i * E_ + e];
    }
    for (int off = 16; off > 0; off >>= 1)
        for (int e = 0; e < E_; e++)
            s[e] += __shfl_down_sync(0xffffffffu, s[e], off);
    if (lane == 0) {
        float se[E_];
        for (int e = 0; e < E_; e++) se[e] = fmaxf(s[e], 0.f);
        int i1 = 0;
        float v1 = se[0];
        for (int e = 1; e < E_; e++) {
            if (se[e] > v1) { v1 = se[e]; i1 = e; }
        }
        int i2 = -1;
        float v2 = -1.f;
        for (int e = 0; e < E_; e++) {
            if (e != i1 && se[e] > v2) { v2 = se[e]; i2 = e; }
        }
        float denom = v1 + v2 + 1e-6f;
        float w1 = v1 / denom;
        float w2 = v2 / denom;
        int p1 = atomicAdd(&cnt[i1], 1);
        list[i1 * T_ + p1] = t;
        int p2 = atomicAdd(&cnt[i2], 1);
        list[i2 * T_ + p2] = t;
        slot_e[t * 2] = i1;
        slot_p[t * 2] = p1;
        slot_w[t * 2] = w1;
        slot_e[t * 2 + 1] = i2;
        slot_p[t * 2 + 1] = p2;
        slot_w[t * 2 + 1] = w2;
    }
}

// ---------------- final combine ----------------
__global__ void combine_kernel(const float* __restrict__ hidden,
                               const float* __restrict__ shout,
                               const float* __restrict__ eout,
                               const int* __restrict__ slot_e,
                               const int* __restrict__ slot_p,
                               const float* __restrict__ slot_w,
                               float* __restrict__ out) {
    int t = blockIdx.x;
    int e0 = slot_e[t * 2];
    int e1 = slot_e[t * 2 + 1];
    int p0 = slot_p[t * 2];
    int p1 = slot_p[t * 2 + 1];
    float w0 = slot_w[t * 2];
    float w1 = slot_w[t * 2 + 1];
    const float* r0 = eout + ((size_t)e0 * T_ + p0) * H_;
    const float* r1 = eout + ((size_t)e1 * T_ + p1) * H_;
    const float* hd = hidden + (size_t)t * H_;
    const float* sh = shout + (size_t)t * H_;
    float* op = out + (size_t)t * H_;
    for (int i = threadIdx.x; i < H_; i += 256)
        op[i] = hd[i] + sh[i] + w0 * r0[i] + w1 * r1[i];
}

// ---------------- launch ----------------
static void conv(const float* src, bf16* h, bf16* l, int n) {
    int blocks = (n / 4 + 255) / 256;
    if (blocks > 2048) blocks = 2048;
    conv_kernel<<<blocks, 256>>>(src, h, l, n);
}

extern "C" void kernel_launch(void* const* d_in, const int* in_sizes,
                              int n_in, void* d_out, int out_size) {
    const float* hs  = (const float*)d_in[0];
    const float* ln1 = (const float*)d_in[1];
    const float* ln2 = (const float*)d_in[2];
    const float* wq  = (const float*)d_in[3];
    const float* wk  = (const float*)d_in[4];
    const float* wv  = (const float*)d_in[5];
    const float* wo  = (const float*)d_in[6];
    const float* rw  = (const float*)d_in[7];
    const float* eg  = (const float*)d_in[8];
    const float* eu  = (const float*)d_in[9];
    const float* ed  = (const float*)d_in[10];
    const float* sg  = (const float*)d_in[11];
    const float* su  = (const float*)d_in[12];
    const float* sd  = (const float*)d_in[13];
    float* out = (float*)d_out;

    float *q, *k, *v, *hidden, *xn2f, *shg, *shu, *shout, *mg, *mu, *eout;
    float *slot_w;
    int *cnt, *list, *slot_e, *slot_p;
    bf16 *xn1h, *xn1l, *attnh, *attnl, *xn2h, *xn2l;
    bf16 *shah, *shal, *mah, *mal;
    bf16 *qph, *qpl, *kph, *kpl, *vph, *vpl;
    bf16 *wqh, *wql, *wkh, *wkl, *wvh, *wvl, *woh, *wol;
    bf16 *sgh, *sgl, *suh, *sul, *sdh, *sdl;
    bf16 *egh, *egl, *euh, *eul, *edh, *edl;

    cudaGetSymbolAddress((void**)&q, g_q);
    cudaGetSymbolAddress((void**)&k, g_k);
    cudaGetSymbolAddress((void**)&v, g_v);
    cudaGetSymbolAddress((void**)&hidden, g_hidden);
    cudaGetSymbolAddress((void**)&xn2f, g_xn2f);
    cudaGetSymbolAddress((void**)&shg, g_shg);
    cudaGetSymbolAddress((void**)&shu, g_shu);
    cudaGetSymbolAddress((void**)&shout, g_shout);
    cudaGetSymbolAddress((void**)&mg, g_mg);
    cudaGetSymbolAddress((void**)&mu, g_mu);
    cudaGetSymbolAddress((void**)&eout, g_eout);
    cudaGetSymbolAddress((void**)&cnt, g_cnt);
    cudaGetSymbolAddress((void**)&list, g_list);
    cudaGetSymbolAddress((void**)&slot_e, g_slot_e);
    cudaGetSymbolAddress((void**)&slot_p, g_slot_p);
    cudaGetSymbolAddress((void**)&slot_w, g_slot_w);
    cudaGetSymbolAddress((void**)&xn1h, g_xn1h);
    cudaGetSymbolAddress((void**)&xn1l, g_xn1l);
    cudaGetSymbolAddress((void**)&attnh, g_attnh);
    cudaGetSymbolAddress((void**)&attnl, g_attnl);
    cudaGetSymbolAddress((void**)&xn2h, g_xn2h);
    cudaGetSymbolAddress((void**)&xn2l, g_xn2l);
    cudaGetSymbolAddress((void**)&shah, g_shah);
    cudaGetSymbolAddress((void**)&shal, g_shal);
    cudaGetSymbolAddress((void**)&mah, g_mah);
    cudaGetSymbolAddress((void**)&mal, g_mal);
    cudaGetSymbolAddress((void**)&qph, g_qph);
    cudaGetSymbolAddress((void**)&qpl, g_qpl);
    cudaGetSymbolAddress((void**)&kph, g_kph);
    cudaGetSymbolAddress((void**)&kpl, g_kpl);
    cudaGetSymbolAddress((void**)&vph, g_vph);
    cudaGetSymbolAddress((void**)&vpl, g_vpl);
    cudaGetSymbolAddress((void**)&wqh, g_wqh);
    cudaGetSymbolAddress((void**)&wql, g_wql);
    cudaGetSymbolAddress((void**)&wkh, g_wkh);
    cudaGetSymbolAddress((void**)&wkl, g_wkl);
    cudaGetSymbolAddress((void**)&wvh, g_wvh);
    cudaGetSymbolAddress((void**)&wvl, g_wvl);
    cudaGetSymbolAddress((void**)&woh, g_woh);
    cudaGetSymbolAddress((void**)&wol, g_wol);
    cudaGetSymbolAddress((void**)&sgh, g_sgh);
    cudaGetSymbolAddress((void**)&sgl, g_sgl);
    cudaGetSymbolAddress((void**)&suh, g_suh);
    cudaGetSymbolAddress((void**)&sul, g_sul);
    cudaGetSymbolAddress((void**)&sdh, g_sdh);
    cudaGetSymbolAddress((void**)&sdl, g_sdl);
    cudaGetSymbolAddress((void**)&egh, g_egh);
    cudaGetSymbolAddress((void**)&egl, g_egl);
    cudaGetSymbolAddress((void**)&euh, g_euh);
    cudaGetSymbolAddress((void**)&eul, g_eul);
    cudaGetSymbolAddress((void**)&edh, g_edh);
    cudaGetSymbolAddress((void**)&edl, g_edl);

    cudaFuncSetAttribute(attn_wmma_kernel,
                         cudaFuncAttributeMaxDynamicSharedMemorySize,
                         ATTN_SMEM2);
    cudaFuncSetAttribute(wmma_gemm_kernel,
                         cudaFuncAttributeMaxDynamicSharedMemorySize,
                         GEMM_SMEM);

    // 0) split weights into bf16 hi/lo
    conv(wq, wqh, wql, H_ * NH_ * HD_);
    conv(wk, wkh, wkl, H_ * NKV_ * HD_);
    conv(wv, wvh, wvl, H_ * NKV_ * HD_);
    conv(wo, woh, wol, NH_ * HD_ * H_);
    conv(sg, sgh, sgl, H_ * I_);
    conv(su, suh, sul, H_ * I_);
    conv(sd, sdh, sdl, I_ * H_);
    conv(eg, egh, egl, E_ * H_ * I_);
    conv(eu, euh, eul, E_ * H_ * I_);
    conv(ed, edh, edl, E_ * I_ * H_);

    // 1) ln1
    rmsnorm_pair_kernel<<<T_, 256>>>(hs, ln1, xn1h, xn1l, (float*)0);
    // 2) qkv projections (tensor cores)
    wmma_gemm_kernel<<<dim3(16, 32, 1), 256, GEMM_SMEM>>>(
        xn1h, xn1l, 0, wqh, wql, 0, q, 0, (const float*)0,
        T_, NH_ * HD_, H_, (const int*)0, (const int*)0);
    wmma_gemm_kernel<<<dim3(4, 32, 1), 256, GEMM_SMEM>>>(
        xn1h, xn1l, 0, wkh, wkl, 0, k, 0, (const float*)0,
        T_, NKV_ * HD_, H_, (const int*)0, (const int*)0);
    wmma_gemm_kernel<<<dim3(4, 32, 1), 256, GEMM_SMEM>>>(
        xn1h, xn1l, 0, wvh, wvl, 0, v, 0, (const float*)0,
        T_, NKV_ * HD_, H_, (const int*)0, (const int*)0);
    // 3) RoPE -> bf16 pairs (scale folded into q); v split too
    rope_pair_kernel<<<(T_ * NH_ * 64 + 255) / 256, 256>>>(
        q, qph, qpl, NH_, 0.08838834764831845f);
    rope_pair_kernel<<<(T_ * NKV_ * 64 + 255) / 256, 256>>>(
        k, kph, kpl, NKV_, 1.0f);
    conv(v, vph, vpl, T_ * NKV_ * HD_);
    // 4) attention (wmma flash)
    attn_wmma_kernel<<<dim3(S_ / 64, NH_, B_), 256, ATTN_SMEM2>>>(
        qph, qpl, kph, kpl, vph, vpl, attnh, attnl);
    // 5) o-proj + residual
    wmma_gemm_kernel<<<dim3(16, 32, 1), 256, GEMM_SMEM>>>(
        attnh, attnl, 0, woh, wol, 0, hidden, 0, hs,
        T_, H_, NH_ * HD_, (const int*)0, (const int*)0);
    // 6) ln2
    rmsnorm_pair_kernel<<<T_, 256>>>(hidden, ln2, xn2h, xn2l, xn2f);
    // 7) shared expert
    wmma_gemm_kernel<<<dim3(8, 32, 1), 256, GEMM_SMEM>>>(
        xn2h, xn2l, 0, sgh, sgl, 0, shg, 0, (const float*)0,
        T_, I_, H_, (const int*)0, (const int*)0);
    wmma_gemm_kernel<<<dim3(8, 32, 1), 256, GEMM_SMEM>>>(
        xn2h, xn2l, 0, suh, sul, 0, shu, 0, (const float*)0,
        T_, I_, H_, (const int*)0, (const int*)0);
    silumul_kernel<<<dim3(T_ * I_ / 1024, 1), 256>>>(
        shg, shu, shah, shal, (const int*)0);
    wmma_gemm_kernel<<<dim3(16, 32, 1), 256, GEMM_SMEM>>>(
        shah, shal, 0, sdh, sdl, 0, shout, 0, (const float*)0,
        T_, H_, I_, (const int*)0, (const int*)0);
    // 8) router + scatter
    zero_cnt_kernel<<<1, 32>>>(cnt);
    router_kernel<<<T_ / 8, 256>>>(xn2f, rw, cnt, list, slot_e, slot_p,
                                   slot_w);
    // 9) routed experts
    wmma_gemm_kernel<<<dim3(8, 32, E_), 256, GEMM_SMEM>>>(
        xn2h, xn2l, 0, egh, egl, (size_t)H_ * I_, mg, (size_t)T_ * I_,
        (const float*)0, T_, I_, H_, cnt, list);
    wmma_gemm_kernel<<<dim3(8, 32, E_), 256, GEMM_SMEM>>>(
        xn2h, xn2l, 0, euh, eul, (size_t)H_ * I_, mu, (size_t)T_ * I_,
        (const float*)0, T_, I_, H_, cnt, list);
    silumul_kernel<<<dim3(T_ * I_ / 1024, E_), 256>>>(mg, mu, mah, mal, cnt);
    wmma_gemm_kernel<<<dim3(16, 32, E_), 256, GEMM_SMEM>>>(
        mah, mal, (size_t)T_ * I_, edh, edl, (size_t)I_ * H_, eout,
        (size_t)T_ * H_, (const float*)0, T_, H_, I_, cnt, (const int*)0);
    // 10) combine
    combine_kernel<<<T_, 256>>>(hidden, shout, eout, slot_e, slot_p,
                                slot_w, out);
}

// round 11
// speedup vs baseline: 1.9327x; 1.0084x over previous
#include <cuda_runtime.h>
#include <cuda_bf16.h>
#include <cuda_pipeline.h>
#include <mma.h>
#include <math.h>

using namespace nvcuda;
typedef __nv_bfloat16 bf16;

// ---------------- problem constants ----------------
constexpr int B_  = 2;
constexpr int S_  = 2048;
constexpr int H_  = 2048;
constexpr int NH_ = 16;
constexpr int NKV_= 4;
constexpr int HD_ = 128;
constexpr int T_  = B_ * S_;
constexpr int E_  = 8;
constexpr int I_  = 1024;
constexpr float EPS_ = 1e-5f;
constexpr float THETA_ = 500000.0f;

// ---------------- scratch (device globals) ----------------
__device__ float g_q[T_ * NH_ * HD_];
__device__ float g_k[T_ * NKV_ * HD_];
__device__ float g_v[T_ * NKV_ * HD_];
__device__ float g_hidden[T_ * H_];
__device__ float g_xn2f[T_ * H_];
__device__ float g_shg[T_ * I_];
__device__ float g_shu[T_ * I_];
__device__ float g_shout[T_ * H_];
__device__ float g_mg[(size_t)E_ * T_ * I_];
__device__ float g_mu[(size_t)E_ * T_ * I_];
__device__ float g_eout[(size_t)E_ * T_ * H_];

__device__ bf16 g_xn1h[T_ * H_];
__device__ bf16 g_xn1l[T_ * H_];
__device__ bf16 g_attnh[T_ * NH_ * HD_];
__device__ bf16 g_attnl[T_ * NH_ * HD_];
__device__ bf16 g_xn2h[T_ * H_];
__device__ bf16 g_xn2l[T_ * H_];
__device__ bf16 g_shah[T_ * I_];
__device__ bf16 g_shal[T_ * I_];
__device__ bf16 g_mah[(size_t)E_ * T_ * I_];
__device__ bf16 g_mal[(size_t)E_ * T_ * I_];

// attention bf16 pair operands
__device__ bf16 g_qph[T_ * NH_ * HD_];
__device__ bf16 g_qpl[T_ * NH_ * HD_];
__device__ bf16 g_kph[T_ * NKV_ * HD_];
__device__ bf16 g_kpl[T_ * NKV_ * HD_];
__device__ bf16 g_vph[T_ * NKV_ * HD_];
__device__ bf16 g_vpl[T_ * NKV_ * HD_];

__device__ bf16 g_wqh[H_ * NH_ * HD_];
__device__ bf16 g_wql[H_ * NH_ * HD_];
__device__ bf16 g_wkh[H_ * NKV_ * HD_];
__device__ bf16 g_wkl[H_ * NKV_ * HD_];
__device__ bf16 g_wvh[H_ * NKV_ * HD_];
__device__ bf16 g_wvl[H_ * NKV_ * HD_];
__device__ bf16 g_woh[NH_ * HD_ * H_];
__device__ bf16 g_wol[NH_ * HD_ * H_];
__device__ bf16 g_sgh[H_ * I_];
__device__ bf16 g_sgl[H_ * I_];
__device__ bf16 g_suh[H_ * I_];
__device__ bf16 g_sul[H_ * I_];
__device__ bf16 g_sdh[I_ * H_];
__device__ bf16 g_sdl[I_ * H_];
__device__ bf16 g_egh[(size_t)E_ * H_ * I_];
__device__ bf16 g_egl[(size_t)E_ * H_ * I_];
__device__ bf16 g_euh[(size_t)E_ * H_ * I_];
__device__ bf16 g_eul[(size_t)E_ * H_ * I_];
__device__ bf16 g_edh[(size_t)E_ * I_ * H_];
__device__ bf16 g_edl[(size_t)E_ * I_ * H_];

__device__ int   g_cnt[E_];
__device__ int   g_list[E_ * T_];
__device__ int   g_slot_e[T_ * 2];
__device__ int   g_slot_p[T_ * 2];
__device__ float g_slot_w[T_ * 2];

// ---------------- fp32 -> bf16 hi/lo split (grid-stride) ----------------
__global__ void conv_kernel(const float* __restrict__ src,
                            bf16* __restrict__ hi,
                            bf16* __restrict__ lo, int n) {
    int stride = gridDim.x * blockDim.x;
    for (int t = blockIdx.x * blockDim.x + threadIdx.x; t * 4 < n;
         t += stride) {
        int i = t * 4;
        float4 v = *(const float4*)(src + i);
        bf16 h0 = __float2bfloat16(v.x);
        bf16 h1 = __float2bfloat16(v.y);
        bf16 h2 = __float2bfloat16(v.z);
        bf16 h3 = __float2bfloat16(v.w);
        bf16 l0 = __float2bfloat16(v.x - __bfloat162float(h0));
        bf16 l1 = __float2bfloat16(v.y - __bfloat162float(h1));
        bf16 l2 = __float2bfloat16(v.z - __bfloat162float(h2));
        bf16 l3 = __float2bfloat16(v.w - __bfloat162float(h3));
        __nv_bfloat162* H2 = (__nv_bfloat162*)(hi + i);
        __nv_bfloat162* L2 = (__nv_bfloat162*)(lo + i);
        H2[0] = __halves2bfloat162(h0, h1);
        H2[1] = __halves2bfloat162(h2, h3);
        L2[0] = __halves2bfloat162(l0, l1);
        L2[1] = __halves2bfloat162(l2, l3);
    }
}

// ---------------- RMSNorm -> bf16 pair (+ optional fp32 copy) ----------------
__global__ void rmsnorm_pair_kernel(const float* __restrict__ in,
                                    const float* __restrict__ w,
                                    bf16* __restrict__ oh,
                                    bf16* __restrict__ ol,
                                    float* __restrict__ of) {
    int t = blockIdx.x;
    const float* x = in + (size_t)t * H_;
    float ss = 0.f;
    for (int i = threadIdx.x; i < H_; i += 256) {
        float vv = x[i];
        ss += vv * vv;
    }
    __shared__ float red[256];
    red[threadIdx.x] = ss;
    __syncthreads();
    for (int s2 = 128; s2 > 0; s2 >>= 1) {
        if (threadIdx.x < s2) red[threadIdx.x] += red[threadIdx.x + s2];
        __syncthreads();
    }
    float rs = rsqrtf(red[0] / (float)H_ + EPS_);
    size_t base = (size_t)t * H_;
    for (int i = threadIdx.x; i < H_; i += 256) {
        float y = w[i] * x[i] * rs;
        bf16 h = __float2bfloat16(y);
        oh[base + i] = h;
        ol[base + i] = __float2bfloat16(y - __bfloat162float(h));
        if (of) of[base + i] = y;
    }
}

// ============================================================================
// padding banner
// ----------------------------------------------------------------------------
// Inline PTX asm string literals get mangled by the submission transport, so
// this file uses only C++ APIs for tensor-core and async-copy work:
// nvcuda::wmma fragments and the cuda_pipeline.h intrinsics. This banner also
// keeps the byte region around line ~250 inside comments.
//
// Round 11 changes:
//  (a) GEMM pipeline deepened to 3 stages (113 KB dynamic smem) to hide more
//      of the ~577-cycle DRAM latency behind wmma compute.
//  (b) Attention now keeps the O accumulator fragments in REGISTERS across
//      all KV steps. The per-row alpha rescale and the final 1/L normalize
//      are applied directly to fragment elements using the stable Volta+
//      fp32 accumulator row mapping for m16n16k16: element e of the 8-elem
//      fragment lives in row (lane>>2) + 8*((e>>1)&1); only the ROW is
//      needed for these row-broadcast scalings, not the column. O is stored
//      to shared memory once, at the end, for the bf16 pair writeback.
//      If this mapping were wrong the bench rel_err would explode; it is the
//      layout used by all Volta..Blackwell mma f32 accumulators.
//  (c) expf -> __expf in softmax and SiLU (MUFU ex2; rel err ~2^-21).
//
// Numerics (bf16x3 split, unchanged): x ~= hi + lo, hi = bf16(x),
// lo = bf16(x - hi); A x B ~= Ah*Bh + Ah*Bl + Al*Bh with fp32 accumulators.
// Layer relative error ~1.2e-5, threshold 1e-3.
// ============================================================================

constexpr int GLDA = 40;    // A smem stride (32 + 8 pad)
constexpr int GLDB = 136;   // B smem stride (128 + 8 pad)
constexpr int ATILE = 128 * GLDA;
constexpr int BTILE = 32 * GLDB;
constexpr int STAGE_ELEMS = 2 * ATILE + 2 * BTILE;   // 18944 bf16
constexpr int NSTAGE = 3;
constexpr int GEMM_SMEM = NSTAGE * STAGE_ELEMS * 2;  // 113664 bytes

__global__ void __launch_bounds__(256)
wmma_gemm_kernel(const bf16* __restrict__ Ah, const bf16* __restrict__ Al,
                 size_t sA,
                 const bf16* __restrict__ Bh, const bf16* __restrict__ Bl,
                 size_t sB,
                 float* __restrict__ C, size_t sC,
                 const float* __restrict__ addend,
                 int M, int N, int K,
                 const int* __restrict__ counts,
                 const int* __restrict__ lists) {
    extern __shared__ __align__(16) bf16 smg[];

    int z = blockIdx.z;
    int Mz = M;
    if (counts) {
        int c = counts[z];
        if (c < Mz) Mz = c;
    }
    int m0 = blockIdx.y * 128;
    if (m0 >= Mz) return;
    int n0 = blockIdx.x * 128;
    Ah += (size_t)z * sA;
    Al += (size_t)z * sA;
    Bh += (size_t)z * sB;
    Bl += (size_t)z * sB;
    C += (size_t)z * sC;
    if (addend) addend += (size_t)z * sC;
    const int* lst = lists ? (lists + (size_t)z * T_) : (const int*)0;

    int tid = threadIdx.x;
    int w = tid >> 5;
    int wm = w >> 1;
    int wn = w & 1;

    int aRow = tid >> 1;
    int aCol = (tid & 1) << 4;
    int bRow = tid >> 3;
    int bCol = (tid & 7) << 4;

    wmma::fragment<wmma::accumulator, 16, 16, 16, float> acc[2][4];
    for (int mi = 0; mi < 2; mi++)
        for (int nj = 0; nj < 4; nj++)
            wmma::fill_fragment(acc[mi][nj], 0.0f);

    int nk = K / 32;

    auto load_stage = [&](int k0, int st) {
        bf16* sAh = smg + st * STAGE_ELEMS;
        bf16* sAl = sAh + ATILE;
        bf16* sBh = sAl + ATILE;
        bf16* sBl = sBh + BTILE;
        int grow = m0 + aRow;
        bf16* dh = sAh + aRow * GLDA + aCol;
        bf16* dl = sAl + aRow * GLDA + aCol;
        if (grow < Mz) {
            int arow = lst ? lst[grow] : grow;
            size_t off = (size_t)arow * K + k0 + aCol;
            __pipeline_memcpy_async(dh, Ah + off, 16);
            __pipeline_memcpy_async(dh + 8, Ah + off + 8, 16);
            __pipeline_memcpy_async(dl, Al + off, 16);
            __pipeline_memcpy_async(dl + 8, Al + off + 8, 16);
        } else {
            int4 zz = make_int4(0, 0, 0, 0);
            *(int4*)dh = zz;
            *(int4*)(dh + 8) = zz;
            *(int4*)dl = zz;
            *(int4*)(dl + 8) = zz;
        }
        size_t boff = (size_t)(k0 + bRow) * N + n0 + bCol;
        bf16* ebh = sBh + bRow * GLDB + bCol;
        bf16* ebl = sBl + bRow * GLDB + bCol;
        __pipeline_memcpy_async(ebh, Bh + boff, 16);
        __pipeline_memcpy_async(ebh + 8, Bh + boff + 8, 16);
        __pipeline_memcpy_async(ebl, Bl + boff, 16);
        __pipeline_memcpy_async(ebl + 8, Bl + boff + 8, 16);
    };

    load_stage(0, 0);
    __pipeline_commit();
    if (nk > 1) {
        load_stage(32, 1);
        __pipeline_commit();
    }

    for (int ki = 0; ki < nk; ki++) {
        if (ki + 2 < nk) {
            load_stage((ki + 2) * 32, (ki + 2) % NSTAGE);
            __pipeline_commit();
            __pipeline_wait_prior(2);
        } else if (ki + 1 < nk) {
            __pipeline_wait_prior(1);
        } else {
            __pipeline_wait_prior(0);
        }
        __syncthreads();

        int st = ki % NSTAGE;
        bf16* sAh = smg + st * STAGE_ELEMS;
        bf16* sAl = sAh + ATILE;
        bf16* sBh = sAl + ATILE;
        bf16* sBl = sBh + BTILE;

        for (int kb = 0; kb < 32; kb += 16) {
            wmma::fragment<wmma::matrix_a, 16, 16, 16, bf16,
                           wmma::row_major> fah[2], fal[2];
            for (int mi = 0; mi < 2; mi++) {
                const bf16* pa = sAh + (wm * 32 + mi * 16) * GLDA + kb;
                wmma::load_matrix_sync(fah[mi], pa, GLDA);
                const bf16* pl = sAl + (wm * 32 + mi * 16) * GLDA + kb;
                wmma::load_matrix_sync(fal[mi], pl, GLDA);
            }
            wmma::fragment<wmma::matrix_b, 16, 16, 16, bf16,
                           wmma::row_major> fbh[4], fbl[4];
            for (int nj = 0; nj < 4; nj++) {
                const bf16* pb = sBh + kb * GLDB + wn * 64 + nj * 16;
                wmma::load_matrix_sync(fbh[nj], pb, GLDB);
                const bf16* pl = sBl + kb * GLDB + wn * 64 + nj * 16;
                wmma::load_matrix_sync(fbl[nj], pl, GLDB);
            }
            for (int mi = 0; mi < 2; mi++) {
                for (int nj = 0; nj < 4; nj++) {
                    wmma::mma_sync(acc[mi][nj], fah[mi], fbh[nj],
                                   acc[mi][nj]);
                    wmma::mma_sync(acc[mi][nj], fah[mi], fbl[nj],
                                   acc[mi][nj]);
                    wmma::mma_sync(acc[mi][nj], fal[mi], fbh[nj],
                                   acc[mi][nj]);
                }
            }
        }
        __syncthreads();
    }

    for (int mi = 0; mi < 2; mi++) {
        for (int nj = 0; nj < 4; nj++) {
            int row = m0 + wm * 32 + mi * 16;
            int col = n0 + wn * 64 + nj * 16;
            float* cp = C + (size_t)row * N + col;
            if (addend) {
                wmma::fragment<wmma::accumulator, 16, 16, 16, float> fc;
                const float* ap = addend + (size_t)row * N + col;
                wmma::load_matrix_sync(fc, ap, N, wmma::mem_row_major);
                for (int e = 0; e < fc.num_elements; e++)
                    acc[mi][nj].x[e] += fc.x[e];
            }
            wmma::store_matrix_sync(cp, acc[mi][nj], N,
                                    wmma::mem_row_major);
        }
    }
}

// ---------------- RoPE -> bf16 hi/lo pair (optionally pre-scaled) ----------
__global__ void rope_pair_kernel(const float* __restrict__ src,
                                 bf16* __restrict__ oh,
                                 bf16* __restrict__ ol,
                                 int nheads, float mul) {
    int idx = blockIdx.x * blockDim.x + threadIdx.x;
    int total = T_ * nheads * (HD_ / 2);
    if (idx >= total) return;
    int d = idx & 63;
    int rest = idx >> 6;
    int h = rest % nheads;
    int t = rest / nheads;
    int pos = t % S_;
    float inv = powf(THETA_, -(float)d / 64.0f);
    float ang = (float)pos * inv;
    float c = cosf(ang);
    float sn = sinf(ang);
    size_t base = (size_t)t * nheads * HD_ + h * HD_;
    float x1 = src[base + d];
    float x2 = src[base + d + 64];
    float y1 = (x1 * c - x2 * sn) * mul;
    float y2 = (x2 * c + x1 * sn) * mul;
    bf16 h1 = __float2bfloat16(y1);
    bf16 h2 = __float2bfloat16(y2);
    oh[base + d] = h1;
    oh[base + d + 64] = h2;
    ol[base + d] = __float2bfloat16(y1 - __bfloat162float(h1));
    ol[base + d + 64] = __float2bfloat16(y2 - __bfloat162float(h2));
}

// ---------------- wmma flash attention (O in registers) ----------------
constexpr int AQLD = 136;   // Q/K/V/O smem stride (128 + 8)
constexpr int ASLD = 72;    // S/P smem stride (64 + 8)
constexpr int ATTN_SMEM2 =
    6 * 64 * AQLD * 2 +            // Qh Ql Kh Kl Vh Vl (bf16)
    64 * ASLD * 4 +                // S (fp32)
    2 * 64 * ASLD * 2 +            // Ph Pl (bf16)
    64 * AQLD * 4 +                // O (fp32, final writeback staging)
    3 * 64 * 4;                    // M L A rows

__global__ void __launch_bounds__(256, 1)
attn_wmma_kernel(const bf16* __restrict__ qh, const bf16* __restrict__ ql,
                 const bf16* __restrict__ kh, const bf16* __restrict__ kl,
                 const bf16* __restrict__ vh, const bf16* __restrict__ vl,
                 bf16* __restrict__ oh, bf16* __restrict__ ol) {
    extern __shared__ char smraw[];
    bf16* Qh = (bf16*)smraw;
    bf16* Ql = Qh + 64 * AQLD;
    bf16* Kh = Ql + 64 * AQLD;
    bf16* Kl = Kh + 64 * AQLD;
    bf16* Vh = Kl + 64 * AQLD;
    bf16* Vl = Vh + 64 * AQLD;
    float* Ss = (float*)(Vl + 64 * AQLD);
    bf16* Ph = (bf16*)(Ss + 64 * ASLD);
    bf16* Pl = Ph + 64 * ASLD;
    float* Os = (float*)(Pl + 64 * ASLD);
    float* Mr = Os + 64 * AQLD;
    float* Lr = Mr + 64;
    float* Ar = Lr + 64;

    int qt = (int)(gridDim.x - 1) - (int)blockIdx.x;  // heavy CTAs first
    int h = blockIdx.y;
    int b = blockIdx.z;
    int hk = h >> 2;
    int tid = threadIdx.x;
    int w = tid >> 5;
    int lane = tid & 31;
    int wm = w >> 1;     // 0..3
    int wn = w & 1;      // 0..1
    int accRow0 = wm * 16 + (lane >> 2);   // rows for fragment elems 0,1,4,5
    int accRow1 = accRow0 + 8;             // rows for fragment elems 2,3,6,7

    // load Q tile (64 x 128, hi+lo), init M/L
    for (int i = tid; i < 64 * 16; i += 256) {
        int row = i >> 4;
        int c8 = (i & 15) << 3;
        int token = b * S_ + qt * 64 + row;
        size_t off = (size_t)token * (NH_ * HD_) + h * HD_ + c8;
        *(int4*)(Qh + row * AQLD + c8) = *(const int4*)(qh + off);
        *(int4*)(Ql + row * AQLD + c8) = *(const int4*)(ql + off);
    }
    if (tid < 64) {
        Mr[tid] = -1e30f;
        Lr[tid] = 0.f;
    }

    // O accumulator in registers: 16 rows x 64 cols per warp
    wmma::fragment<wmma::accumulator, 16, 16, 16, float> oacc[4];
    for (int nj = 0; nj < 4; nj++)
        wmma::fill_fragment(oacc[nj], 0.0f);
    __syncthreads();

    for (int kt = 0; kt <= qt; kt++) {
        // load K/V tiles (hi+lo)
        for (int i = tid; i < 64 * 16; i += 256) {
            int row = i >> 4;
            int c8 = (i & 15) << 3;
            int token = b * S_ + kt * 64 + row;
            size_t off = (size_t)token * (NKV_ * HD_) + hk * HD_ + c8;
            *(int4*)(Kh + row * AQLD + c8) = *(const int4*)(kh + off);
            *(int4*)(Kl + row * AQLD + c8) = *(const int4*)(kl + off);
            *(int4*)(Vh + row * AQLD + c8) = *(const int4*)(vh + off);
            *(int4*)(Vl + row * AQLD + c8) = *(const int4*)(vl + off);
        }
        __syncthreads();

        // S = Q K^T (3-term). warp tile 16x32 of the 64x64 score tile.
        {
            wmma::fragment<wmma::accumulator, 16, 16, 16, float> sacc[2];
            wmma::fill_fragment(sacc[0], 0.0f);
            wmma::fill_fragment(sacc[1], 0.0f);
            for (int ks = 0; ks < 8; ks++) {
                wmma::fragment<wmma::matrix_a, 16, 16, 16, bf16,
                               wmma::row_major> fqh, fql;
                const bf16* pq = Qh + (wm * 16) * AQLD + ks * 16;
                wmma::load_matrix_sync(fqh, pq, AQLD);
                const bf16* pq2 = Ql + (wm * 16) * AQLD + ks * 16;
                wmma::load_matrix_sync(fql, pq2, AQLD);
                for (int nj = 0; nj < 2; nj++) {
                    wmma::fragment<wmma::matrix_b, 16, 16, 16, bf16,
                                   wmma::col_major> fkh, fkl;
                    const bf16* pk =
                        Kh + (wn * 32 + nj * 16) * AQLD + ks * 16;
                    wmma::load_matrix_sync(fkh, pk, AQLD);
                    const bf16* pk2 =
                        Kl + (wn * 32 + nj * 16) * AQLD + ks * 16;
                    wmma::load_matrix_sync(fkl, pk2, AQLD);
                    wmma::mma_sync(sacc[nj], fqh, fkh, sacc[nj]);
                    wmma::mma_sync(sacc[nj], fqh, fkl, sacc[nj]);
                    wmma::mma_sync(sacc[nj], fql, fkh, sacc[nj]);
                }
            }
            for (int nj = 0; nj < 2; nj++) {
                float* ps = Ss + (wm * 16) * ASLD + wn * 32 + nj * 16;
                wmma::store_matrix_sync(ps, sacc[nj], ASLD,
                                        wmma::mem_row_major);
            }
        }
        __syncthreads();

        // online softmax: 4 threads per row, 16 columns each
        {
            int r = tid >> 2;
            int sub = tid & 3;
            int c0 = sub * 16;
            bool diag = (kt == qt);
            float mOld = Mr[r];
            float mx = mOld;
            for (int c = c0; c < c0 + 16; c++) {
                float val = Ss[r * ASLD + c];
                if (diag && c > r) val = -1e30f;
                mx = fmaxf(mx, val);
            }
            mx = fmaxf(mx, __shfl_xor_sync(0xffffffffu, mx, 1));
            mx = fmaxf(mx, __shfl_xor_sync(0xffffffffu, mx, 2));
            float sum = 0.f;
            for (int c = c0; c < c0 + 16; c++) {
                float val = Ss[r * ASLD + c];
                if (diag && c > r) val = -1e30f;
                float p = __expf(val - mx);
                bf16 phv = __float2bfloat16(p);
                Ph[r * ASLD + c] = phv;
                Pl[r * ASLD + c] =
                    __float2bfloat16(p - __bfloat162float(phv));
                sum += p;
            }
            sum += __shfl_xor_sync(0xffffffffu, sum, 1);
            sum += __shfl_xor_sync(0xffffffffu, sum, 2);
            if (sub == 0) {
                float alpha = __expf(mOld - mx);
                Lr[r] = Lr[r] * alpha + sum;
                Mr[r] = mx;
                Ar[r] = alpha;
            }
        }
        __syncthreads();

        // rescale O fragments in registers by per-row alpha
        {
            float a0 = Ar[accRow0];
            float a1 = Ar[accRow1];
            for (int nj = 0; nj < 4; nj++) {
                for (int e = 0; e < 8; e++) {
                    oacc[nj].x[e] *= (e & 2) ? a1 : a0;
                }
            }
        }

        // O += P V (3-term), accumulating in registers.
        for (int ks = 0; ks < 4; ks++) {
            wmma::fragment<wmma::matrix_a, 16, 16, 16, bf16,
                           wmma::row_major> fph, fpl;
            const bf16* pp = Ph + (wm * 16) * ASLD + ks * 16;
            wmma::load_matrix_sync(fph, pp, ASLD);
            const bf16* pp2 = Pl + (wm * 16) * ASLD + ks * 16;
            wmma::load_matrix_sync(fpl, pp2, ASLD);
            for (int nj = 0; nj < 4; nj++) {
                wmma::fragment<wmma::matrix_b, 16, 16, 16, bf16,
                               wmma::row_major> fvh, fvl;
                const bf16* pv =
                    Vh + (ks * 16) * AQLD + wn * 64 + nj * 16;
                wmma::load_matrix_sync(fvh, pv, AQLD);
                const bf16* pv2 =
                    Vl + (ks * 16) * AQLD + wn * 64 + nj * 16;
                wmma::load_matrix_sync(fvl, pv2, AQLD);
                wmma::mma_sync(oacc[nj], fph, fvh, oacc[nj]);
                wmma::mma_sync(oacc[nj], fph, fvl, oacc[nj]);
                wmma::mma_sync(oacc[nj], fpl, fvh, oacc[nj]);
            }
        }
        __syncthreads();
    }

    // final: normalize in registers, stage through smem, write bf16 pairs
    {
        float i0 = 1.0f / Lr[accRow0];
        float i1 = 1.0f / Lr[accRow1];
        for (int nj = 0; nj < 4; nj++) {
            for (int e = 0; e < 8; e++) {
                oacc[nj].x[e] *= (e & 2) ? i1 : i0;
            }
            float* po = Os + (wm * 16) * AQLD + wn * 64 + nj * 16;
            wmma::store_matrix_sync(po, oacc[nj], AQLD,
                                    wmma::mem_row_major);
        }
    }
    __syncthreads();

    for (int i = tid; i < 64 * 32; i += 256) {
        int r = i >> 5;
        int c4 = (i & 31) << 2;
        int token = b * S_ + qt * 64 + r;
        size_t off = (size_t)token * (NH_ * HD_) + h * HD_ + c4;
        for (int j = 0; j < 4; j++) {
            float val = Os[r * AQLD + c4 + j];
            bf16 hv = __float2bfloat16(val);
            oh[off + j] = hv;
            ol[off + j] = __float2bfloat16(val - __bfloat162float(hv));
        }
    }
}

// ---------------- SiLU(g)*u -> bf16 pair ----------------
__global__ void silumul_kernel(const float* __restrict__ g,
                               const float* __restrict__ u,
                               bf16* __restrict__ oh,
                               bf16* __restrict__ ol,
                               const int* __restrict__ counts) {
    int z = blockIdx.y;
    int M = counts ? counts[z] : T_;
    int idx = (blockIdx.x * 256 + threadIdx.x) * 4;
    if (idx >= T_ * I_) return;
    if ((idx / I_) >= M) return;
    size_t base = (size_t)z * T_ * I_ + idx;
    float4 gv = *(const float4*)(g + base);
    float4 uv = *(const float4*)(u + base);
    float a0 = gv.x / (1.f + __expf(-gv.x)) * uv.x;
    float a1 = gv.y / (1.f + __expf(-gv.y)) * uv.y;
    float a2 = gv.z / (1.f + __expf(-gv.z)) * uv.z;
    float a3 = gv.w / (1.f + __expf(-gv.w)) * uv.w;
    bf16 h0 = __float2bfloat16(a0);
    bf16 h1 = __float2bfloat16(a1);
    bf16 h2 = __float2bfloat16(a2);
    bf16 h3 = __float2bfloat16(a3);
    __nv_bfloat162* H2 = (__nv_bfloat162*)(oh + base);
    __nv_bfloat162* L2 = (__nv_bfloat162*)(ol + base);
    H2[0] = __halves2bfloat162(h0, h1);
    H2[1] = __halves2bfloat162(h2, h3);
    bf16 l0 = __float2bfloat16(a0 - __bfloat162float(h0));
    bf16 l1 = __float2bfloat16(a1 - __bfloat162float(h1));
    bf16 l2 = __float2bfloat16(a2 - __bfloat162float(h2));
    bf16 l3 = __float2bfloat16(a3 - __bfloat162float(h3));
    L2[0] = __halves2bfloat162(l0, l1);
    L2[1] = __halves2bfloat162(l2, l3);
}

// ---------------- router ----------------
__global__ void zero_cnt_kernel(int* cnt) {
    if (threadIdx.x < E_) cnt[threadIdx.x] = 0;
}

__global__ void router_kernel(const float* __restrict__ xn2,
                              const float* __restrict__ rw,
                              int* __restrict__ cnt, int* __restrict__ list,
                              int* __restrict__ slot_e,
                              int* __restrict__ slot_p,
                              float* __restrict__ slot_w) {
    int t = blockIdx.x * 8 + (threadIdx.x >> 5);
    int lane = threadIdx.x & 31;
    if (t >= T_) return;
    const float* x = xn2 + (size_t)t * H_;
    float s[E_];
    for (int e = 0; e < E_; e++) s[e] = 0.f;
    for (int i = lane; i < H_; i += 32) {
        float xv = x[i];
        for (int e = 0; e < E_; e++) s[e] += xv * rw[i * E_ + e];
    }
    for (int off = 16; off > 0; off >>= 1)
        for (int e = 0; e < E_; e++)
            s[e] += __shfl_down_sync(0xffffffffu, s[e], off);
    if (lane == 0) {
        float se[E_];
        for (int e = 0; e < E_; e++) se[e] = fmaxf(s[e], 0.f);
        int i1 = 0;
        float v1 = se[0];
        for (int e = 1; e < E_; e++) {
            if (se[e] > v1) { v1 = se[e]; i1 = e; }
        }
        int i2 = -1;
        float v2 = -1.f;
        for (int e = 0; e < E_; e++) {
            if (e != i1 && se[e] > v2) { v2 = se[e]; i2 = e; }
        }
        float denom = v1 + v2 + 1e-6f;
        float w1 = v1 / denom;
        float w2 = v2 / denom;
        int p1 = atomicAdd(&cnt[i1], 1);
        list[i1 * T_ + p1] = t;
        int p2 = atomicAdd(&cnt[i2], 1);
        list[i2 * T_ + p2] = t;
        slot_e[t * 2] = i1;
        slot_p[t * 2] = p1;
        slot_w[t * 2] = w1;
        slot_e[t * 2 + 1] = i2;
        slot_p[t * 2 + 1] = p2;
        slot_w[t * 2 + 1] = w2;
    }
}

// ---------------- final combine ----------------
__global__ void combine_kernel(const float* __restrict__ hidden,
                               const float* __restrict__ shout,
                               const float* __restrict__ eout,
                               const int* __restrict__ slot_e,
                               const int* __restrict__ slot_p,
                               const float* __restrict__ slot_w,
                               float* __restrict__ out) {
    int t = blockIdx.x;
    int e0 = slot_e[t * 2];
    int e1 = slot_e[t * 2 + 1];
    int p0 = slot_p[t * 2];
    int p1 = slot_p[t * 2 + 1];
    float w0 = slot_w[t * 2];
    float w1 = slot_w[t * 2 + 1];
    const float* r0 = eout + ((size_t)e0 * T_ + p0) * H_;
    const float* r1 = eout + ((size_t)e1 * T_ + p1) * H_;
    const float* hd = hidden + (size_t)t * H_;
    const float* sh = shout + (size_t)t * H_;
    float* op = out + (size_t)t * H_;
    for (int i = threadIdx.x; i < H_; i += 256)
        op[i] = hd[i] + sh[i] + w0 * r0[i] + w1 * r1[i];
}

// ---------------- launch ----------------
static void conv(const float* src, bf16* h, bf16* l, int n) {
    int blocks = (n / 4 + 255) / 256;
    if (blocks > 2048) blocks = 2048;
    conv_kernel<<<blocks, 256>>>(src, h, l, n);
}

extern "C" void kernel_launch(void* const* d_in, const int* in_sizes,
                              int n_in, void* d_out, int out_size) {
    const float* hs  = (const float*)d_in[0];
    const float* ln1 = (const float*)d_in[1];
    const float* ln2 = (const float*)d_in[2];
    const float* wq  = (const float*)d_in[3];
    const float* wk  = (const float*)d_in[4];
    const float* wv  = (const float*)d_in[5];
    const float* wo  = (const float*)d_in[6];
    const float* rw  = (const float*)d_in[7];
    const float* eg  = (const float*)d_in[8];
    const float* eu  = (const float*)d_in[9];
    const float* ed  = (const float*)d_in[10];
    const float* sg  = (const float*)d_in[11];
    const float* su  = (const float*)d_in[12];
    const float* sd  = (const float*)d_in[13];
    float* out = (float*)d_out;

    float *q, *k, *v, *hidden, *xn2f, *shg, *shu, *shout, *mg, *mu, *eout;
    float *slot_w;
    int *cnt, *list, *slot_e, *slot_p;
    bf16 *xn1h, *xn1l, *attnh, *attnl, *xn2h, *xn2l;
    bf16 *shah, *shal, *mah, *mal;
    bf16 *qph, *qpl, *kph, *kpl, *vph, *vpl;
    bf16 *wqh, *wql, *wkh, *wkl, *wvh, *wvl, *woh, *wol;
    bf16 *sgh, *sgl, *suh, *sul, *sdh, *sdl;
    bf16 *egh, *egl, *euh, *eul, *edh, *edl;

    cudaGetSymbolAddress((void**)&q, g_q);
    cudaGetSymbolAddress((void**)&k, g_k);
    cudaGetSymbolAddress((void**)&v, g_v);
    cudaGetSymbolAddress((void**)&hidden, g_hidden);
    cudaGetSymbolAddress((void**)&xn2f, g_xn2f);
    cudaGetSymbolAddress((void**)&shg, g_shg);
    cudaGetSymbolAddress((void**)&shu, g_shu);
    cudaGetSymbolAddress((void**)&shout, g_shout);
    cudaGetSymbolAddress((void**)&mg, g_mg);
    cudaGetSymbolAddress((void**)&mu, g_mu);
    cudaGetSymbolAddress((void**)&eout, g_eout);
    cudaGetSymbolAddress((void**)&cnt, g_cnt);
    cudaGetSymbolAddress((void**)&list, g_list);
    cudaGetSymbolAddress((void**)&slot_e, g_slot_e);
    cudaGetSymbolAddress((void**)&slot_p, g_slot_p);
    cudaGetSymbolAddress((void**)&slot_w, g_slot_w);
    cudaGetSymbolAddress((void**)&xn1h, g_xn1h);
    cudaGetSymbolAddress((void**)&xn1l, g_xn1l);
    cudaGetSymbolAddress((void**)&attnh, g_attnh);
    cudaGetSymbolAddress((void**)&attnl, g_attnl);
    cudaGetSymbolAddress((void**)&xn2h, g_xn2h);
    cudaGetSymbolAddress((void**)&xn2l, g_xn2l);
    cudaGetSymbolAddress((void**)&shah, g_shah);
    cudaGetSymbolAddress((void**)&shal, g_shal);
    cudaGetSymbolAddress((void**)&mah, g_mah);
    cudaGetSymbolAddress((void**)&mal, g_mal);
    cudaGetSymbolAddress((void**)&qph, g_qph);
    cudaGetSymbolAddress((void**)&qpl, g_qpl);
    cudaGetSymbolAddress((void**)&kph, g_kph);
    cudaGetSymbolAddress((void**)&kpl, g_kpl);
    cudaGetSymbolAddress((void**)&vph, g_vph);
    cudaGetSymbolAddress((void**)&vpl, g_vpl);
    cudaGetSymbolAddress((void**)&wqh, g_wqh);
    cudaGetSymbolAddress((void**)&wql, g_wql);
    cudaGetSymbolAddress((void**)&wkh, g_wkh);
    cudaGetSymbolAddress((void**)&wkl, g_wkl);
    cudaGetSymbolAddress((void**)&wvh, g_wvh);
    cudaGetSymbolAddress((void**)&wvl, g_wvl);
    cudaGetSymbolAddress((void**)&woh, g_woh);
    cudaGetSymbolAddress((void**)&wol, g_wol);
    cudaGetSymbolAddress((void**)&sgh, g_sgh);
    cudaGetSymbolAddress((void**)&sgl, g_sgl);
    cudaGetSymbolAddress((void**)&suh, g_suh);
    cudaGetSymbolAddress((void**)&sul, g_sul);
    cudaGetSymbolAddress((void**)&sdh, g_sdh);
    cudaGetSymbolAddress((void**)&sdl, g_sdl);
    cudaGetSymbolAddress((void**)&egh, g_egh);
    cudaGetSymbolAddress((void**)&egl, g_egl);
    cudaGetSymbolAddress((void**)&euh, g_euh);
    cudaGetSymbolAddress((void**)&eul, g_eul);
    cudaGetSymbolAddress((void**)&edh, g_edh);
    cudaGetSymbolAddress((void**)&edl, g_edl);

    cudaFuncSetAttribute(attn_wmma_kernel,
                         cudaFuncAttributeMaxDynamicSharedMemorySize,
                         ATTN_SMEM2);
    cudaFuncSetAttribute(wmma_gemm_kernel,
                         cudaFuncAttributeMaxDynamicSharedMemorySize,
                         GEMM_SMEM);

    // 0) split weights into bf16 hi/lo
    conv(wq, wqh, wql, H_ * NH_ * HD_);
    conv(wk, wkh, wkl, H_ * NKV_ * HD_);
    conv(wv, wvh, wvl, H_ * NKV_ * HD_);
    conv(wo, woh, wol, NH_ * HD_ * H_);
    conv(sg, sgh, sgl, H_ * I_);
    conv(su, suh, sul, H_ * I_);
    conv(sd, sdh, sdl, I_ * H_);
    conv(eg, egh, egl, E_ * H_ * I_);
    conv(eu, euh, eul, E_ * H_ * I_);
    conv(ed, edh, edl, E_ * I_ * H_);

    // 1) ln1
    rmsnorm_pair_kernel<<<T_, 256>>>(hs, ln1, xn1h, xn1l, (float*)0);
    // 2) qkv projections (tensor cores)
    wmma_gemm_kernel<<<dim3(16, 32, 1), 256, GEMM_SMEM>>>(
        xn1h, xn1l, 0, wqh, wql, 0, q, 0, (const float*)0,
        T_, NH_ * HD_, H_, (const int*)0, (const int*)0);
    wmma_gemm_kernel<<<dim3(4, 32, 1), 256, GEMM_SMEM>>>(
        xn1h, xn1l, 0, wkh, wkl, 0, k, 0, (const float*)0,
        T_, NKV_ * HD_, H_, (const int*)0, (const int*)0);
    wmma_gemm_kernel<<<dim3(4, 32, 1), 256, GEMM_SMEM>>>(
        xn1h, xn1l, 0, wvh, wvl, 0, v, 0, (const float*)0,
        T_, NKV_ * HD_, H_, (const int*)0, (const int*)0);
    // 3) RoPE -> bf16 pairs (scale folded into q); v split too
    rope_pair_kernel<<<(T_ * NH_ * 64 + 255) / 256, 256>>>(
        q, qph, qpl, NH_, 0.08838834764831845f);
    rope_pair_kernel<<<(T_ * NKV_ * 64 + 255) / 256, 256>>>(
        k, kph, kpl, NKV_, 1.0f);
    conv(v, vph, vpl, T_ * NKV_ * HD_);
    // 4) attention (wmma flash, O in registers)
    attn_wmma_kernel<<<dim3(S_ / 64, NH_, B_), 256, ATTN_SMEM2>>>(
        qph, qpl, kph, kpl, vph, vpl, attnh, attnl);
    // 5) o-proj + residual
    wmma_gemm_kernel<<<dim3(16, 32, 1), 256, GEMM_SMEM>>>(
        attnh, attnl, 0, woh, wol, 0, hidden, 0, hs,
        T_, H_, NH_ * HD_, (const int*)0, (const int*)0);
    // 6) ln2
    rmsnorm_pair_kernel<<<T_, 256>>>(hidden, ln2, xn2h, xn2l, xn2f);
    // 7) shared expert
    wmma_gemm_kernel<<<dim3(8, 32, 1), 256, GEMM_SMEM>>>(
        xn2h, xn2l, 0, sgh, sgl, 0, shg, 0, (const float*)0,
        T_, I_, H_, (const int*)0, (const int*)0);
    wmma_gemm_kernel<<<dim3(8, 32, 1), 256, GEMM_SMEM>>>(
        xn2h, xn2l, 0, suh, sul, 0, shu, 0, (const float*)0,
        T_, I_, H_, (const int*)0, (const int*)0);
    silumul_kernel<<<dim3(T_ * I_ / 1024, 1), 256>>>(
        shg, shu, shah, shal, (const int*)0);
    wmma_gemm_kernel<<<dim3(16, 32, 1), 256, GEMM_SMEM>>>(
        shah, shal, 0, sdh, sdl, 0, shout, 0, (const float*)0,
        T_, H_, I_, (const int*)0, (const int*)0);
    // 8) router + scatter
    zero_cnt_kernel<<<1, 32>>>(cnt);
    router_kernel<<<T_ / 8, 256>>>(xn2f, rw, cnt, list, slot_e, slot_p,
                                   slot_w);
    // 9) routed experts
    wmma_gemm_kernel<<<dim3(8, 32, E_), 256, GEMM_SMEM>>>(
        xn2h, xn2l, 0, egh, egl, (size_t)H_ * I_, mg, (size_t)T_ * I_,
        (const float*)0, T_, I_, H_, cnt, list);
    wmma_gemm_kernel<<<dim3(8, 32, E_), 256, GEMM_SMEM>>>(
        xn2h, xn2l, 0, euh, eul, (size_t)H_ * I_, mu, (size_t)T_ * I_,
        (const float*)0, T_, I_, H_, cnt, list);
    silumul_kernel<<<dim3(T_ * I_ / 1024, E_), 256>>>(mg, mu, mah, mal, cnt);
    wmma_gemm_kernel<<<dim3(16, 32, E_), 256, GEMM_SMEM>>>(
        mah, mal, (size_t)T_ * I_, edh, edl, (size_t)I_ * H_, eout,
        (size_t)T_ * H_, (const float*)0, T_, H_, I_, cnt, (const int*)0);
    // 10) combine
    combine_kernel<<<T_, 256>>>(hidden, shout, eout, slot_e, slot_p,
                                slot_w, out);
}